// round 3
// baseline (speedup 1.0000x reference)
#include <cuda_runtime.h>
#include <cstdint>

#define DF 128
#define NMAX 50048

// ---------------- scratch (no allocations allowed) ----------------
__device__ __align__(128) float g_buf1[NMAX * DF];   // (1+eps)*x + agg
__device__ __align__(128) float g_buf2[NMAX * DF];   // t1 (pre-BN layer-1 output)
__device__ __align__(128) float g_W1T[DF * DF];      // W1 transposed (k-major)
__device__ __align__(128) float g_W2T[DF * DF];
__device__ __align__(128) float g_stats[512];        // [sum1|sq1|sum2|sq2]
__device__ __align__(128) float g_bn[512];           // [scale1|shift1|scale2|shift2]
__device__ int g_is64;                               // edge_index dtype flag

// ---------------- detect edge_index dtype (int64 vs int32) ----------------
// If the buffer is little-endian int64 with values < 2^31, every odd 32-bit
// word is 0. For int32 data those words are random node indices (p(0) ~ 2e-5).
__global__ void detect_kernel(const int* __restrict__ ei) {
    if (threadIdx.x == 0) {
        int allz = 1;
        #pragma unroll
        for (int i = 0; i < 8; i++)
            if (ei[2 * i + 1] != 0) allz = 0;
        g_is64 = allz;
    }
}

// ---------------- init: g_buf1 = (1+eps)*x, zero stats ----------------
__global__ void init_kernel(const float* __restrict__ x, const float* __restrict__ eps, int n32) {
    int i = blockIdx.x * blockDim.x + threadIdx.x;
    if (i < 512) g_stats[i] = 0.f;
    if (i < n32) {
        float s = 1.f + __ldg(eps);
        float4 v = __ldg((const float4*)x + i);
        v.x *= s; v.y *= s; v.z *= s; v.w *= s;
        ((float4*)g_buf1)[i] = v;
    }
}

// ---------------- weight transpose: g_W?T[k][j] = W[j][k] ----------------
__global__ void transpose_kernel(const float* __restrict__ W1, const float* __restrict__ W2) {
    const float* src = blockIdx.x ? W2 : W1;
    float* dst = blockIdx.x ? g_W2T : g_W1T;
    __shared__ float tile[32][33];
    int tx = threadIdx.x & 31;
    int ty8 = threadIdx.x >> 5;  // 0..7
    for (int bi = 0; bi < 4; bi++)
        for (int bj = 0; bj < 4; bj++) {
            __syncthreads();
            #pragma unroll
            for (int rr = 0; rr < 32; rr += 8)
                tile[ty8 + rr][tx] = src[(bi * 32 + ty8 + rr) * DF + bj * 32 + tx];
            __syncthreads();
            #pragma unroll
            for (int rr = 0; rr < 32; rr += 8)
                dst[(bj * 32 + ty8 + rr) * DF + bi * 32 + tx] = tile[tx][ty8 + rr];
        }
}

// ---------------- scatter: one warp per edge, vectorized fp32 atomics ----------------
__global__ void scatter_kernel(const float* __restrict__ x, const void* __restrict__ eiv,
                               int E, int n) {
    int t = blockIdx.x * blockDim.x + threadIdx.x;
    int e = t >> 5;
    if (e >= E) return;
    int lane = t & 31;
    int r, c;
    if (g_is64) {
        const long long* ei = (const long long*)eiv;
        r = (int)__ldg(ei + e);
        c = (int)__ldg(ei + E + e);
    } else {
        const int* ei = (const int*)eiv;
        r = __ldg(ei + e);
        c = __ldg(ei + E + e);
    }
    if ((unsigned)r >= (unsigned)n || (unsigned)c >= (unsigned)n) return;
    float4 v = __ldg((const float4*)(x + (size_t)c * DF) + lane);
    float* dst = g_buf1 + (size_t)r * DF + lane * 4;
    asm volatile("red.global.add.v4.f32 [%0], {%1,%2,%3,%4};"
                 :: "l"(dst), "f"(v.x), "f"(v.y), "f"(v.z), "f"(v.w) : "memory");
}

// ---------------- fused GEMM (+optional input BN/ReLU) + column stats ----------------
// BM=BN=K=128, 256 threads, 8x8 register tile per thread.
// LAYER 1: A=g_buf1 -> Out=g_buf2, stats -> g_stats[0..255]
// LAYER 2: A=relu(bn1(g_buf2)) -> Out=d_out (pre-BN), stats -> g_stats[256..511]
template <int LAYER>
__global__ __launch_bounds__(256, 1) void gemm_bn_kernel(const float* __restrict__ bias,
                                                         float* __restrict__ outParam, int n) {
    extern __shared__ float sm[];
    float* sA = sm;                  // 128 x 132 (padded, 16B-aligned rows)
    float* sB = sm + 128 * 132;      // 128 x 128, k-major (sB[k][j] = W[j][k])
    float* sSum = sB + 128 * 128;    // 128
    float* sSq  = sSum + 128;        // 128

    const float* A  = (LAYER == 1) ? g_buf1 : g_buf2;
    const float* WT = (LAYER == 1) ? g_W1T : g_W2T;
    float* Out      = (LAYER == 1) ? g_buf2 : outParam;
    float* gSum     = g_stats + (LAYER == 1 ? 0 : 256);
    float* gSq      = g_stats + (LAYER == 1 ? 128 : 384);

    int tid = threadIdx.x;
    int tx = tid & 15, ty = tid >> 4;
    int row0 = blockIdx.x * 128;

    // stage W^T (coalesced, conflict-free)
    {
        const float4* src = (const float4*)WT;
        float4* dst = (float4*)sB;
        #pragma unroll
        for (int i = 0; i < 16; i++) dst[tid + 256 * i] = src[tid + 256 * i];
    }
    if (tid < 128) { sSum[tid] = 0.f; sSq[tid] = 0.f; }

    // stage A tile (rows beyond n -> zeros); layer2 applies BN1 + ReLU on load
    {
        int m0 = tid >> 5;   // 0..7
        int c4 = tid & 31;   // float4 column
        float4 sc, sh;
        if (LAYER == 2) {
            sc = __ldg((const float4*)g_bn + c4);
            sh = __ldg((const float4*)(g_bn + 128) + c4);
        }
        #pragma unroll
        for (int i = 0; i < 16; i++) {
            int m = m0 + 8 * i;
            int gr = row0 + m;
            float4 v = make_float4(0.f, 0.f, 0.f, 0.f);
            if (gr < n) {
                v = __ldg((const float4*)(A + (size_t)gr * DF) + c4);
                if (LAYER == 2) {
                    v.x = fmaxf(fmaf(v.x, sc.x, sh.x), 0.f);
                    v.y = fmaxf(fmaf(v.y, sc.y, sh.y), 0.f);
                    v.z = fmaxf(fmaf(v.z, sc.z, sh.z), 0.f);
                    v.w = fmaxf(fmaf(v.w, sc.w, sh.w), 0.f);
                }
            }
            *(float4*)(sA + m * 132 + c4 * 4) = v;
        }
    }
    __syncthreads();

    float acc[8][8];
    #pragma unroll
    for (int i = 0; i < 8; i++)
        #pragma unroll
        for (int j = 0; j < 8; j++) acc[i][j] = 0.f;

    const float* aBase = sA + (ty * 4) * 132;
    #pragma unroll 4
    for (int k = 0; k < 128; k++) {
        float4 b0 = ((const float4*)(sB + k * 128))[tx];
        float4 b1 = ((const float4*)(sB + k * 128))[tx + 16];
        float a[8];
        #pragma unroll
        for (int ii = 0; ii < 4; ii++) {
            a[ii]     = aBase[ii * 132 + k];
            a[ii + 4] = aBase[(64 + ii) * 132 + k];
        }
        #pragma unroll
        for (int ii = 0; ii < 8; ii++) {
            acc[ii][0] = fmaf(a[ii], b0.x, acc[ii][0]);
            acc[ii][1] = fmaf(a[ii], b0.y, acc[ii][1]);
            acc[ii][2] = fmaf(a[ii], b0.z, acc[ii][2]);
            acc[ii][3] = fmaf(a[ii], b0.w, acc[ii][3]);
            acc[ii][4] = fmaf(a[ii], b1.x, acc[ii][4]);
            acc[ii][5] = fmaf(a[ii], b1.y, acc[ii][5]);
            acc[ii][6] = fmaf(a[ii], b1.z, acc[ii][6]);
            acc[ii][7] = fmaf(a[ii], b1.w, acc[ii][7]);
        }
    }

    // epilogue: +bias, store pre-BN, accumulate column sum/sumsq
    float4 ba = __ldg((const float4*)bias + tx);
    float4 bb = __ldg((const float4*)bias + 16 + tx);
    float cs[8], cq[8];
    #pragma unroll
    for (int j = 0; j < 8; j++) { cs[j] = 0.f; cq[j] = 0.f; }

    #pragma unroll
    for (int ii = 0; ii < 8; ii++) {
        int r = (ii < 4) ? (ty * 4 + ii) : (64 + ty * 4 + (ii - 4));
        int gr = row0 + r;
        if (gr < n) {
            float v[8];
            v[0] = acc[ii][0] + ba.x; v[1] = acc[ii][1] + ba.y;
            v[2] = acc[ii][2] + ba.z; v[3] = acc[ii][3] + ba.w;
            v[4] = acc[ii][4] + bb.x; v[5] = acc[ii][5] + bb.y;
            v[6] = acc[ii][6] + bb.z; v[7] = acc[ii][7] + bb.w;
            float4* orow = (float4*)(Out + (size_t)gr * DF);
            orow[tx]      = make_float4(v[0], v[1], v[2], v[3]);
            orow[16 + tx] = make_float4(v[4], v[5], v[6], v[7]);
            #pragma unroll
            for (int j = 0; j < 8; j++) { cs[j] += v[j]; cq[j] += v[j] * v[j]; }
        }
    }
    #pragma unroll
    for (int j = 0; j < 4; j++) {
        atomicAdd(&sSum[tx * 4 + j], cs[j]);
        atomicAdd(&sSq [tx * 4 + j], cq[j]);
        atomicAdd(&sSum[64 + tx * 4 + j], cs[4 + j]);
        atomicAdd(&sSq [64 + tx * 4 + j], cq[4 + j]);
    }
    __syncthreads();
    if (tid < 128) {
        atomicAdd(&gSum[tid], sSum[tid]);
        atomicAdd(&gSq [tid], sSq [tid]);
    }
}

// ---------------- BN finalize: scale/shift from sums ----------------
__global__ void finalize_kernel(const float* __restrict__ gamma, const float* __restrict__ beta,
                                int which, float invN) {
    int j = threadIdx.x;  // 128 threads
    float sum = g_stats[which * 256 + j];
    float sq  = g_stats[which * 256 + 128 + j];
    float mean = sum * invN;
    float var = sq * invN - mean * mean;
    float sc = __ldg(gamma + j) * rsqrtf(var + 1e-5f);
    float sh = __ldg(beta + j) - mean * sc;
    g_bn[which * 256 + j] = sc;
    g_bn[which * 256 + 128 + j] = sh;
}

// ---------------- final BN2 + ReLU in place on d_out ----------------
__global__ void apply_kernel(float* __restrict__ out, int n32) {
    int i = blockIdx.x * blockDim.x + threadIdx.x;
    if (i >= n32) return;
    int c4 = i & 31;
    float4 sc = __ldg((const float4*)(g_bn + 256) + c4);
    float4 sh = __ldg((const float4*)(g_bn + 384) + c4);
    float4 v = ((float4*)out)[i];
    v.x = fmaxf(fmaf(v.x, sc.x, sh.x), 0.f);
    v.y = fmaxf(fmaf(v.y, sc.y, sh.y), 0.f);
    v.z = fmaxf(fmaf(v.z, sc.z, sh.z), 0.f);
    v.w = fmaxf(fmaf(v.w, sc.w, sh.w), 0.f);
    ((float4*)out)[i] = v;
}

// ---------------- launch ----------------
extern "C" void kernel_launch(void* const* d_in, const int* in_sizes, int n_in,
                              void* d_out, int out_size) {
    const float* x        = (const float*)d_in[0];
    const void* ei        = d_in[1];
    const float* eps      = (const float*)d_in[2];
    const float* W1       = (const float*)d_in[3];
    const float* b1       = (const float*)d_in[4];
    const float* gamma1   = (const float*)d_in[5];
    const float* beta1    = (const float*)d_in[6];
    const float* W2       = (const float*)d_in[7];
    const float* b2       = (const float*)d_in[8];
    const float* gamma2   = (const float*)d_in[9];
    const float* beta2    = (const float*)d_in[10];
    float* out = (float*)d_out;

    int n   = in_sizes[0] / DF;
    int E   = in_sizes[1] / 2;
    int n32 = n * (DF / 4);

    const int SMEM = (128 * 132 + 128 * 128 + 256) * 4;
    cudaFuncSetAttribute(gemm_bn_kernel<1>, cudaFuncAttributeMaxDynamicSharedMemorySize, SMEM);
    cudaFuncSetAttribute(gemm_bn_kernel<2>, cudaFuncAttributeMaxDynamicSharedMemorySize, SMEM);

    detect_kernel<<<1, 32>>>((const int*)ei);
    init_kernel<<<(n32 + 255) / 256, 256>>>(x, eps, n32);
    transpose_kernel<<<2, 256>>>(W1, W2);
    scatter_kernel<<<(E * 32 + 255) / 256, 256>>>(x, ei, E, n);

    int gblocks = (n + 127) / 128;
    gemm_bn_kernel<1><<<gblocks, 256, SMEM>>>(b1, nullptr, n);
    finalize_kernel<<<1, 128>>>(gamma1, beta1, 0, 1.f / (float)n);
    gemm_bn_kernel<2><<<gblocks, 256, SMEM>>>(b2, out, n);
    finalize_kernel<<<1, 128>>>(gamma2, beta2, 1, 1.f / (float)n);
    apply_kernel<<<(n32 + 255) / 256, 256>>>(out, n32);
}

// round 5
// speedup vs baseline: 1.1728x; 1.1728x over previous
#include <cuda_runtime.h>
#include <cstdint>

#define DF 128
#define NMAX 50048

// ======================= scratch (no allocations allowed) =======================
__device__ __align__(128) float g_buf1[NMAX * DF];     // (1+eps)*x + agg
__device__ __align__(128) float g_buf2[NMAX * DF];     // pre-BN layer-1 output
__device__ __align__(128) float g_Bimg[2 * 32768];     // per layer: fragment-packed W hi/lo
__device__ __align__(128) float g_stats[512];          // [sum1|sq1|sum2|sq2]
__device__ __align__(128) float g_bn[512];             // [scale1|shift1|scale2|shift2]
__device__ int g_is64;

// ======================= helpers =======================
__device__ __forceinline__ uint32_t to_tf32_bits(float a) {
    uint32_t r; asm("cvt.rna.tf32.f32 %0, %1;" : "=r"(r) : "f"(a)); return r;
}
__device__ __forceinline__ void mma8(float* d, uint32_t a0, uint32_t a1, uint32_t a2, uint32_t a3,
                                     uint32_t b0, uint32_t b1) {
    asm volatile("mma.sync.aligned.m16n8k8.row.col.f32.tf32.tf32.f32 "
                 "{%0,%1,%2,%3},{%4,%5,%6,%7},{%8,%9},{%0,%1,%2,%3};"
                 : "+f"(d[0]), "+f"(d[1]), "+f"(d[2]), "+f"(d[3])
                 : "r"(a0), "r"(a1), "r"(a2), "r"(a3), "r"(b0), "r"(b1));
}

// ======================= small kernels =======================
__global__ void detect_kernel(const int* __restrict__ ei) {
    if (threadIdx.x == 0) {
        int allz = 1;
        #pragma unroll
        for (int i = 0; i < 8; i++) if (ei[2 * i + 1] != 0) allz = 0;
        g_is64 = allz;
    }
}

__global__ void init_kernel(const float* __restrict__ x, const float* __restrict__ eps, int n32) {
    int i = blockIdx.x * blockDim.x + threadIdx.x;
    if (i < 512) g_stats[i] = 0.f;
    if (i < n32) {
        float s = 1.f + __ldg(eps);
        float4 v = __ldg((const float4*)x + i);
        v.x *= s; v.y *= s; v.z *= s; v.w *= s;
        ((float4*)g_buf1)[i] = v;
    }
}

// Pack W[n][k] into mma-fragment image: per (nt,ks,lane): {b0h, b1h, b0l, b1l}
// b0 = W[n = nt*8 + lane/4][k = ks*8 + lane%4], b1 = same with k+4.
__global__ void prep_w(const float* __restrict__ W1, const float* __restrict__ W2) {
    const float* W = blockIdx.x ? W2 : W1;
    float* img = g_Bimg + blockIdx.x * 32768;
    for (int idx = threadIdx.x; idx < 16384; idx += 256) {
        int n = idx >> 7, k = idx & 127;
        float v = __ldg(W + idx);
        uint32_t hib = to_tf32_bits(v);
        float hi = __uint_as_float(hib);
        float lo = v - hi;
        int nt = n >> 3, ks = k >> 3;
        int lane = (n & 7) * 4 + (k & 3);
        int half = (k >> 2) & 1;
        int base = ((nt * 16 + ks) * 32 + lane) * 4;
        img[base + half] = hi;
        img[base + 2 + half] = lo;
    }
}

// ---------------- scatter: 4 edges per warp, loads batched before reds ----------------
__global__ void scatter_kernel(const float* __restrict__ x, const void* __restrict__ eiv,
                               int E, int n) {
    int w = (blockIdx.x * blockDim.x + threadIdx.x) >> 5;
    int lane = threadIdx.x & 31;
    int base = w * 4;
    if (base >= E) return;
    float4 v[4];
    int r[4];
    int ok[4];
    #pragma unroll
    for (int i = 0; i < 4; i++) {
        int e = base + i;
        ok[i] = 0;
        if (e < E) {
            int rr, cc;
            if (g_is64) {
                const long long* ei = (const long long*)eiv;
                rr = (int)__ldg(ei + e);
                cc = (int)__ldg(ei + E + e);
            } else {
                const int* ei = (const int*)eiv;
                rr = __ldg(ei + e);
                cc = __ldg(ei + E + e);
            }
            if ((unsigned)rr < (unsigned)n && (unsigned)cc < (unsigned)n) {
                ok[i] = 1;
                r[i] = rr;
                v[i] = __ldg((const float4*)(x + (size_t)cc * DF) + lane);
            }
        }
    }
    #pragma unroll
    for (int i = 0; i < 4; i++) {
        if (ok[i]) {
            float* dst = g_buf1 + (size_t)r[i] * DF + lane * 4;
            asm volatile("red.global.add.v4.f32 [%0], {%1,%2,%3,%4};"
                         :: "l"(dst), "f"(v[i].x), "f"(v[i].y), "f"(v[i].z), "f"(v[i].w) : "memory");
        }
    }
}

// ======================= tf32 mma.sync GEMM + BN stats =======================
// SMEM floats: sSum[128] | sSq[128] | sAh[8192] | sAl[8192] | sB[32768]
#define SM_SUM 0
#define SM_SQ  128
#define SM_AH  256
#define SM_AL  (256 + 8192)
#define SM_B   (256 + 16384)
#define SMEM_FLOATS (256 + 16384 + 32768)

// Stage a 128x64 A chunk (k cols [kc*64, kc*64+64)) into fragment layout with hi/lo split.
template <int LAYER>
__device__ __forceinline__ void stageA(const float* __restrict__ A, int row0, int n, int kc,
                                       float* __restrict__ sAh, float* __restrict__ sAl, int tid) {
    #pragma unroll
    for (int i = 0; i < 8; i++) {
        int id = tid + 256 * i;          // 0..2047
        int m = id >> 4;                 // row in tile
        int f4c = id & 15;               // float4 col within chunk
        int gr = row0 + m;
        float4 v = make_float4(0.f, 0.f, 0.f, 0.f);
        if (gr < n) {
            v = __ldg((const float4*)(A + (size_t)gr * DF) + kc * 16 + f4c);
            if (LAYER == 2) {
                float4 sc = __ldg((const float4*)g_bn + kc * 16 + f4c);
                float4 sh = __ldg((const float4*)(g_bn + 128) + kc * 16 + f4c);
                v.x = fmaxf(fmaf(v.x, sc.x, sh.x), 0.f);
                v.y = fmaxf(fmaf(v.y, sc.y, sh.y), 0.f);
                v.z = fmaxf(fmaf(v.z, sc.z, sh.z), 0.f);
                v.w = fmaxf(fmaf(v.w, sc.w, sh.w), 0.f);
            }
        }
        int g = m >> 4;
        int ks = f4c >> 1;
        int slot = (f4c & 1) * 2 + ((m >> 3) & 1);   // 2*(khigh) + rhigh
        float vv[4] = {v.x, v.y, v.z, v.w};
        #pragma unroll
        for (int j = 0; j < 4; j++) {
            uint32_t hib = to_tf32_bits(vv[j]);
            float hi = __uint_as_float(hib);
            float lo = vv[j] - hi;
            int lane_s = ((m & 7) * 4 + j) ^ (ks & 7);   // bank swizzle
            int fi = ((g * 8 + ks) * 32 + lane_s) * 4 + slot;
            sAh[fi] = hi;
            sAl[fi] = lo;
        }
    }
}

template <int LAYER>
__global__ __launch_bounds__(256, 1) void gemm_tc(const float* __restrict__ bias,
                                                  float* __restrict__ outParam, int n) {
    extern __shared__ float smf[];
    float* sAh = smf + SM_AH;
    float* sAl = smf + SM_AL;
    float* sB  = smf + SM_B;

    int tid = threadIdx.x, wid = tid >> 5, lane = tid & 31;
    int warpM = wid & 3, warpN = wid >> 2;
    int row0 = blockIdx.x * 128;

    const float* A    = (LAYER == 1) ? g_buf1 : g_buf2;
    const float* Bimg = g_Bimg + (LAYER == 1 ? 0 : 32768);
    float* Out        = (LAYER == 1) ? g_buf2 : outParam;
    float* gSum       = g_stats + (LAYER == 1 ? 0 : 256);
    float* gSq        = g_stats + (LAYER == 1 ? 128 : 384);

    if (tid < 128) { smf[SM_SUM + tid] = 0.f; smf[SM_SQ + tid] = 0.f; }

    // stage full B fragment image (32768 floats = 8192 uint4)
    {
        const uint4* src = (const uint4*)Bimg;
        uint4* dst = (uint4*)sB;
        #pragma unroll
        for (int i = 0; i < 32; i++) dst[tid + 256 * i] = __ldg(src + tid + 256 * i);
    }

    float acc[2][8][4];
    #pragma unroll
    for (int mt = 0; mt < 2; mt++)
        #pragma unroll
        for (int nt = 0; nt < 8; nt++)
            #pragma unroll
            for (int j = 0; j < 4; j++) acc[mt][nt][j] = 0.f;

    const uint4* B4 = (const uint4*)sB;

    #pragma unroll 1
    for (int kc = 0; kc < 2; kc++) {
        __syncthreads();                       // previous chunk consumed
        stageA<LAYER>(A, row0, n, kc, sAh, sAl, tid);
        __syncthreads();

        const uint4* A4h = (const uint4*)sAh;
        const uint4* A4l = (const uint4*)sAl;

        #pragma unroll
        for (int ks = 0; ks < 8; ks++) {
            int lane_s = lane ^ (ks & 7);
            int g0 = warpM * 2;
            uint4 ah0 = A4h[(g0 * 8 + ks) * 32 + lane_s];
            uint4 al0 = A4l[(g0 * 8 + ks) * 32 + lane_s];
            uint4 ah1 = A4h[((g0 + 1) * 8 + ks) * 32 + lane_s];
            uint4 al1 = A4l[((g0 + 1) * 8 + ks) * 32 + lane_s];
            int ksg = kc * 8 + ks;
            #pragma unroll
            for (int nt = 0; nt < 8; nt++) {
                uint4 b = B4[((warpN * 8 + nt) * 16 + ksg) * 32 + lane];
                // d += Ah*Bh + Ah*Bl + Al*Bh
                mma8(acc[0][nt], ah0.x, ah0.y, ah0.z, ah0.w, b.x, b.y);
                mma8(acc[0][nt], ah0.x, ah0.y, ah0.z, ah0.w, b.z, b.w);
                mma8(acc[0][nt], al0.x, al0.y, al0.z, al0.w, b.x, b.y);
                mma8(acc[1][nt], ah1.x, ah1.y, ah1.z, ah1.w, b.x, b.y);
                mma8(acc[1][nt], ah1.x, ah1.y, ah1.z, ah1.w, b.z, b.w);
                mma8(acc[1][nt], al1.x, al1.y, al1.z, al1.w, b.x, b.y);
            }
        }
    }

    // ---------------- register epilogue: bias, store, BN stats ----------------
    float cs[16], cq[16];
    #pragma unroll
    for (int j = 0; j < 16; j++) { cs[j] = 0.f; cq[j] = 0.f; }

    int rbase = row0 + warpM * 32 + (lane >> 2);
    #pragma unroll
    for (int nt = 0; nt < 8; nt++) {
        int C = warpN * 64 + nt * 8 + (lane & 3) * 2;
        float2 bb = __ldg((const float2*)(bias + C));
        #pragma unroll
        for (int mt = 0; mt < 2; mt++) {
            int R0 = rbase + mt * 16;
            int R1 = R0 + 8;
            float v00 = acc[mt][nt][0] + bb.x;
            float v01 = acc[mt][nt][1] + bb.y;
            float v10 = acc[mt][nt][2] + bb.x;
            float v11 = acc[mt][nt][3] + bb.y;
            if (R0 < n) {
                *(float2*)(Out + (size_t)R0 * DF + C) = make_float2(v00, v01);
                cs[nt * 2] += v00; cq[nt * 2] += v00 * v00;
                cs[nt * 2 + 1] += v01; cq[nt * 2 + 1] += v01 * v01;
            }
            if (R1 < n) {
                *(float2*)(Out + (size_t)R1 * DF + C) = make_float2(v10, v11);
                cs[nt * 2] += v10; cq[nt * 2] += v10 * v10;
                cs[nt * 2 + 1] += v11; cq[nt * 2 + 1] += v11 * v11;
            }
        }
    }
    // reduce over lanes sharing the same columns (stride-4 lane groups)
    #pragma unroll
    for (int off = 4; off < 32; off <<= 1) {
        #pragma unroll
        for (int j = 0; j < 16; j++) {
            cs[j] += __shfl_xor_sync(0xFFFFFFFF, cs[j], off);
            cq[j] += __shfl_xor_sync(0xFFFFFFFF, cq[j], off);
        }
    }
    if (lane < 4) {
        #pragma unroll
        for (int nt = 0; nt < 8; nt++) {
            int C = warpN * 64 + nt * 8 + lane * 2;
            atomicAdd(&smf[SM_SUM + C], cs[nt * 2]);
            atomicAdd(&smf[SM_SUM + C + 1], cs[nt * 2 + 1]);
            atomicAdd(&smf[SM_SQ + C], cq[nt * 2]);
            atomicAdd(&smf[SM_SQ + C + 1], cq[nt * 2 + 1]);
        }
    }
    __syncthreads();
    if (tid < 128) {
        atomicAdd(&gSum[tid], smf[SM_SUM + tid]);
        atomicAdd(&gSq[tid],  smf[SM_SQ + tid]);
    }
}

// ======================= BN finalize & final apply =======================
__global__ void finalize_kernel(const float* __restrict__ gamma, const float* __restrict__ beta,
                                int which, float invN) {
    int j = threadIdx.x;  // 128
    float sum = g_stats[which * 256 + j];
    float sq  = g_stats[which * 256 + 128 + j];
    float mean = sum * invN;
    float var = sq * invN - mean * mean;
    float sc = __ldg(gamma + j) * rsqrtf(var + 1e-5f);
    float sh = __ldg(beta + j) - mean * sc;
    g_bn[which * 256 + j] = sc;
    g_bn[which * 256 + 128 + j] = sh;
}

__global__ void apply_kernel(float* __restrict__ out, int n32) {
    int i = blockIdx.x * blockDim.x + threadIdx.x;
    if (i >= n32) return;
    int c4 = i & 31;
    float4 sc = __ldg((const float4*)(g_bn + 256) + c4);
    float4 sh = __ldg((const float4*)(g_bn + 384) + c4);
    float4 v = ((float4*)out)[i];
    v.x = fmaxf(fmaf(v.x, sc.x, sh.x), 0.f);
    v.y = fmaxf(fmaf(v.y, sc.y, sh.y), 0.f);
    v.z = fmaxf(fmaf(v.z, sc.z, sh.z), 0.f);
    v.w = fmaxf(fmaf(v.w, sc.w, sh.w), 0.f);
    ((float4*)out)[i] = v;
}

// ======================= launch =======================
extern "C" void kernel_launch(void* const* d_in, const int* in_sizes, int n_in,
                              void* d_out, int out_size) {
    const float* x      = (const float*)d_in[0];
    const void* ei      = d_in[1];
    const float* eps    = (const float*)d_in[2];
    const float* W1     = (const float*)d_in[3];
    const float* b1     = (const float*)d_in[4];
    const float* gamma1 = (const float*)d_in[5];
    const float* beta1  = (const float*)d_in[6];
    const float* W2     = (const float*)d_in[7];
    const float* b2     = (const float*)d_in[8];
    const float* gamma2 = (const float*)d_in[9];
    const float* beta2  = (const float*)d_in[10];
    float* out = (float*)d_out;

    int n   = in_sizes[0] / DF;
    int E   = in_sizes[1] / 2;
    int n32 = n * (DF / 4);

    const int SMEM = SMEM_FLOATS * 4;  // 197632 bytes
    cudaFuncSetAttribute(gemm_tc<1>, cudaFuncAttributeMaxDynamicSharedMemorySize, SMEM);
    cudaFuncSetAttribute(gemm_tc<2>, cudaFuncAttributeMaxDynamicSharedMemorySize, SMEM);

    detect_kernel<<<1, 32>>>((const int*)ei);
    init_kernel<<<(n32 + 255) / 256, 256>>>(x, eps, n32);
    prep_w<<<2, 256>>>(W1, W2);

    int warps = (E + 3) / 4;
    int sblocks = (warps * 32 + 255) / 256;
    scatter_kernel<<<sblocks, 256>>>(x, ei, E, n);

    int gblocks = (n + 127) / 128;
    gemm_tc<1><<<gblocks, 256, SMEM>>>(b1, nullptr, n);
    finalize_kernel<<<1, 128>>>(gamma1, beta1, 0, 1.f / (float)n);
    gemm_tc<2><<<gblocks, 256, SMEM>>>(b2, out, n);
    finalize_kernel<<<1, 128>>>(gamma2, beta2, 1, 1.f / (float)n);
    apply_kernel<<<(n32 + 255) / 256, 256>>>(out, n32);
}

// round 6
// speedup vs baseline: 1.4512x; 1.2374x over previous
#include <cuda_runtime.h>
#include <cuda_bf16.h>
#include <cstdint>

#define DF 128
#define NMAX 50048

// ======================= scratch (no allocations allowed) =======================
__device__ __align__(128) float g_buf1[NMAX * DF];   // (1+eps)*x + agg
__device__ __align__(128) float g_buf2[NMAX * DF];   // pre-BN layer-1 output
__device__ __align__(128) uint4 g_Bimg[2 * 4096];    // per layer: packed W frags {b0h,b1h,b0l,b1l}
__device__ __align__(128) float g_stats[512];        // [sum1|sq1|sum2|sq2]
__device__ int g_is64;

// ======================= helpers =======================
__device__ __forceinline__ void mma16(float* d, uint4 a, uint32_t b0, uint32_t b1) {
    asm volatile("mma.sync.aligned.m16n8k16.row.col.f32.bf16.bf16.f32 "
                 "{%0,%1,%2,%3},{%4,%5,%6,%7},{%8,%9},{%0,%1,%2,%3};"
                 : "+f"(d[0]), "+f"(d[1]), "+f"(d[2]), "+f"(d[3])
                 : "r"(a.x), "r"(a.y), "r"(a.z), "r"(a.w), "r"(b0), "r"(b1));
}
__device__ __forceinline__ uint32_t pack2(float lo_e, float hi_e) {
    __nv_bfloat162 h = __floats2bfloat162_rn(lo_e, hi_e);  // .x = low half
    return *reinterpret_cast<uint32_t*>(&h);
}

// ======================= fused init: scale x, zero stats, pack W, detect dtype ===
__device__ void prep_w_block(const float* __restrict__ W, uint4* __restrict__ img) {
    for (int idx = threadIdx.x; idx < 16384; idx += 256) {
        int nn = idx >> 7, k = idx & 127;
        float v = __ldg(W + idx);
        __nv_bfloat16 hb = __float2bfloat16(v);
        __nv_bfloat16 lb = __float2bfloat16(v - __bfloat162float(hb));
        int nt = nn >> 3, kstep = k >> 4, kk = k & 15;
        int lane = (nn & 7) * 4 + ((kk & 7) >> 1);
        int reg = (kk >> 3) & 1;
        int half = kk & 1;
        __nv_bfloat16* p = (__nv_bfloat16*)(img + (nt * 8 + kstep) * 32 + lane);
        p[reg * 2 + half] = hb;       // .x/.y words = hi
        p[4 + reg * 2 + half] = lb;   // .z/.w words = lo
    }
}

__global__ void fused_init(const float* __restrict__ x, const float* __restrict__ eps,
                           const float* __restrict__ W1, const float* __restrict__ W2,
                           const int* __restrict__ ei, int n32, int NB) {
    if ((int)blockIdx.x >= NB) {
        int wb = blockIdx.x - NB;
        prep_w_block(wb ? W2 : W1, g_Bimg + wb * 4096);
        if (wb == 0 && threadIdx.x == 0) {
            int allz = 1;
            #pragma unroll
            for (int i = 0; i < 8; i++) if (ei[2 * i + 1] != 0) allz = 0;
            g_is64 = allz;
        }
        return;
    }
    int i = blockIdx.x * blockDim.x + threadIdx.x;
    if (i < 512) g_stats[i] = 0.f;
    if (i < n32) {
        float s = 1.f + __ldg(eps);
        float4 v = __ldg((const float4*)x + i);
        v.x *= s; v.y *= s; v.z *= s; v.w *= s;
        ((float4*)g_buf1)[i] = v;
    }
}

// ======================= scatter: 4 edges/warp, batched loads, v4 reds ==========
__global__ void scatter_kernel(const float* __restrict__ x, const void* __restrict__ eiv,
                               int E, int n) {
    int w = (blockIdx.x * blockDim.x + threadIdx.x) >> 5;
    int lane = threadIdx.x & 31;
    int base = w * 4;
    if (base >= E) return;
    float4 v[4];
    int r[4], ok[4];
    #pragma unroll
    for (int i = 0; i < 4; i++) {
        int e = base + i;
        ok[i] = 0;
        if (e < E) {
            int rr, cc;
            if (g_is64) {
                const long long* ei = (const long long*)eiv;
                rr = (int)__ldg(ei + e);
                cc = (int)__ldg(ei + E + e);
            } else {
                const int* ei = (const int*)eiv;
                rr = __ldg(ei + e);
                cc = __ldg(ei + E + e);
            }
            if ((unsigned)rr < (unsigned)n && (unsigned)cc < (unsigned)n) {
                ok[i] = 1; r[i] = rr;
                v[i] = __ldg((const float4*)(x + (size_t)cc * DF) + lane);
            }
        }
    }
    #pragma unroll
    for (int i = 0; i < 4; i++) {
        if (ok[i]) {
            float* dst = g_buf1 + (size_t)r[i] * DF + lane * 4;
            asm volatile("red.global.add.v4.f32 [%0], {%1,%2,%3,%4};"
                         :: "l"(dst), "f"(v[i].x), "f"(v[i].y), "f"(v[i].z), "f"(v[i].w) : "memory");
        }
    }
}

// ======================= bf16 split-MMA GEMM + BN stats =======================
// SMEM floats: sSum[128] | sSq[128] | sBn[256] | sAh[4096] | sAl[4096] | sB[16384]
#define SM_SUM 0
#define SM_SQ  128
#define SM_BN  256
#define SM_AH  512
#define SM_AL  (512 + 4096)
#define SM_B   (512 + 8192)
#define SMEM_FLOATS (512 + 8192 + 16384)   // 25088 floats = 100352 B

template <int LAYER>
__device__ __forceinline__ void stageA(const float* __restrict__ A, int row0, int nrows, int kc,
                                       uint32_t* __restrict__ sAh, uint32_t* __restrict__ sAl,
                                       const float* __restrict__ sBn, int tid) {
    #pragma unroll
    for (int i = 0; i < 8; i++) {
        int id = tid + 256 * i;    // 0..2047
        int m = id >> 4;           // 0..127
        int f4c = id & 15;         // float4 col within 64-col chunk
        int gr = row0 + m;
        float4 v = make_float4(0.f, 0.f, 0.f, 0.f);
        if (gr < nrows) {
            v = __ldg((const float4*)(A + (size_t)gr * DF) + kc * 16 + f4c);
            if (LAYER == 2) {
                int c = (kc * 16 + f4c) * 4;
                v.x = fmaxf(fmaf(v.x, sBn[c + 0], sBn[128 + c + 0]), 0.f);
                v.y = fmaxf(fmaf(v.y, sBn[c + 1], sBn[128 + c + 1]), 0.f);
                v.z = fmaxf(fmaf(v.z, sBn[c + 2], sBn[128 + c + 2]), 0.f);
                v.w = fmaxf(fmaf(v.w, sBn[c + 3], sBn[128 + c + 3]), 0.f);
            }
        }
        int g = m >> 4, mr = m & 15;
        int kstep = f4c >> 2;
        int L0 = (mr & 7) * 4 + (f4c & 1) * 2;          // lanes L0, L0+1
        int r = (((f4c >> 1) & 1) << 1) + (mr >> 3);    // reg slot
        uint32_t h01 = pack2(v.x, v.y);
        uint32_t h23 = pack2(v.z, v.w);
        __nv_bfloat162* hp01 = (__nv_bfloat162*)&h01;
        __nv_bfloat162* hp23 = (__nv_bfloat162*)&h23;
        uint32_t l01 = pack2(v.x - __bfloat162float(hp01->x), v.y - __bfloat162float(hp01->y));
        uint32_t l23 = pack2(v.z - __bfloat162float(hp23->x), v.w - __bfloat162float(hp23->y));
        int base = ((g * 4 + kstep) * 32 + L0) * 4 + r;
        sAh[base] = h01;
        sAh[base + 4] = h23;
        sAl[base] = l01;
        sAl[base + 4] = l23;
    }
}

template <int LAYER>
__global__ __launch_bounds__(256, 2) void gemm_tc(const float* __restrict__ bias,
                                                  const float* __restrict__ gamma1,
                                                  const float* __restrict__ beta1,
                                                  float* __restrict__ outParam, int n, float invN) {
    extern __shared__ float smf[];
    uint32_t* sAh = (uint32_t*)(smf + SM_AH);
    uint32_t* sAl = (uint32_t*)(smf + SM_AL);
    const uint4* B4 = (const uint4*)(smf + SM_B);
    float* sBn = smf + SM_BN;

    int tid = threadIdx.x, wid = tid >> 5, lane = tid & 31;
    int warpM = wid & 3, warpN = wid >> 2;
    int row0 = blockIdx.x * 128;

    const float* A = (LAYER == 1) ? g_buf1 : g_buf2;
    const uint4* Bimg = g_Bimg + (LAYER == 1 ? 0 : 4096);
    float* Out = (LAYER == 1) ? g_buf2 : outParam;
    float* gSum = g_stats + (LAYER == 1 ? 0 : 256);
    float* gSq  = g_stats + (LAYER == 1 ? 128 : 384);

    if (tid < 128) {
        smf[SM_SUM + tid] = 0.f;
        smf[SM_SQ + tid] = 0.f;
        if (LAYER == 2) {  // fold BN1 finalize into prologue
            float sum = g_stats[tid], sq = g_stats[128 + tid];
            float mean = sum * invN;
            float var = sq * invN - mean * mean;
            float sc = __ldg(gamma1 + tid) * rsqrtf(var + 1e-5f);
            sBn[tid] = sc;
            sBn[128 + tid] = __ldg(beta1 + tid) - mean * sc;
        }
    }
    // stage full B fragment image (4096 uint4)
    {
        uint4* dst = (uint4*)(smf + SM_B);
        #pragma unroll
        for (int i = 0; i < 16; i++) dst[tid + 256 * i] = __ldg(Bimg + tid + 256 * i);
    }

    float acc[2][8][4];
    #pragma unroll
    for (int mt = 0; mt < 2; mt++)
        #pragma unroll
        for (int nt = 0; nt < 8; nt++)
            #pragma unroll
            for (int j = 0; j < 4; j++) acc[mt][nt][j] = 0.f;

    int g0 = warpM * 2;
    const uint4* A4h = (const uint4*)sAh;
    const uint4* A4l = (const uint4*)sAl;

    #pragma unroll 1
    for (int kc = 0; kc < 2; kc++) {
        __syncthreads();   // B/bn ready (kc=0) or previous chunk consumed
        stageA<LAYER>(A, row0, n, kc, sAh, sAl, sBn, tid);
        __syncthreads();
        #pragma unroll
        for (int kk = 0; kk < 4; kk++) {
            int ksG = kc * 4 + kk;
            uint4 ah0 = A4h[(g0 * 4 + kk) * 32 + lane];
            uint4 al0 = A4l[(g0 * 4 + kk) * 32 + lane];
            uint4 ah1 = A4h[((g0 + 1) * 4 + kk) * 32 + lane];
            uint4 al1 = A4l[((g0 + 1) * 4 + kk) * 32 + lane];
            #pragma unroll
            for (int nt = 0; nt < 8; nt++) {
                uint4 b = B4[((warpN * 8 + nt) * 8 + ksG) * 32 + lane];
                mma16(acc[0][nt], ah0, b.x, b.y);   // Ah*Bh
                mma16(acc[0][nt], al0, b.x, b.y);   // Al*Bh
                mma16(acc[0][nt], ah0, b.z, b.w);   // Ah*Bl
                mma16(acc[1][nt], ah1, b.x, b.y);
                mma16(acc[1][nt], al1, b.x, b.y);
                mma16(acc[1][nt], ah1, b.z, b.w);
            }
        }
    }

    // ---------------- epilogue: bias, store, BN stats ----------------
    float cs[16], cq[16];
    #pragma unroll
    for (int j = 0; j < 16; j++) { cs[j] = 0.f; cq[j] = 0.f; }

    int rbase = row0 + warpM * 32 + (lane >> 2);
    #pragma unroll
    for (int nt = 0; nt < 8; nt++) {
        int C = warpN * 64 + nt * 8 + (lane & 3) * 2;
        float2 bb = __ldg((const float2*)(bias + C));
        #pragma unroll
        for (int mt = 0; mt < 2; mt++) {
            int R0 = rbase + mt * 16;
            int R1 = R0 + 8;
            float v00 = acc[mt][nt][0] + bb.x;
            float v01 = acc[mt][nt][1] + bb.y;
            float v10 = acc[mt][nt][2] + bb.x;
            float v11 = acc[mt][nt][3] + bb.y;
            if (R0 < n) {
                *(float2*)(Out + (size_t)R0 * DF + C) = make_float2(v00, v01);
                cs[nt * 2] += v00;     cq[nt * 2] += v00 * v00;
                cs[nt * 2 + 1] += v01; cq[nt * 2 + 1] += v01 * v01;
            }
            if (R1 < n) {
                *(float2*)(Out + (size_t)R1 * DF + C) = make_float2(v10, v11);
                cs[nt * 2] += v10;     cq[nt * 2] += v10 * v10;
                cs[nt * 2 + 1] += v11; cq[nt * 2 + 1] += v11 * v11;
            }
        }
    }
    #pragma unroll
    for (int off = 4; off < 32; off <<= 1) {
        #pragma unroll
        for (int j = 0; j < 16; j++) {
            cs[j] += __shfl_xor_sync(0xFFFFFFFF, cs[j], off);
            cq[j] += __shfl_xor_sync(0xFFFFFFFF, cq[j], off);
        }
    }
    if (lane < 4) {
        #pragma unroll
        for (int nt = 0; nt < 8; nt++) {
            int C = warpN * 64 + nt * 8 + lane * 2;
            atomicAdd(&smf[SM_SUM + C], cs[nt * 2]);
            atomicAdd(&smf[SM_SUM + C + 1], cs[nt * 2 + 1]);
            atomicAdd(&smf[SM_SQ + C], cq[nt * 2]);
            atomicAdd(&smf[SM_SQ + C + 1], cq[nt * 2 + 1]);
        }
    }
    __syncthreads();
    if (tid < 128) {
        atomicAdd(&gSum[tid], smf[SM_SUM + tid]);
        atomicAdd(&gSq[tid],  smf[SM_SQ + tid]);
    }
}

// ======================= final BN2 + ReLU (finalize fused per-block) ===========
__global__ void apply_kernel(float* __restrict__ out, const float* __restrict__ gamma2,
                             const float* __restrict__ beta2, int n32, float invN) {
    __shared__ float sc[128], sh[128];
    int tid = threadIdx.x;
    if (tid < 128) {
        float sum = g_stats[256 + tid], sq = g_stats[384 + tid];
        float mean = sum * invN;
        float var = sq * invN - mean * mean;
        float s = __ldg(gamma2 + tid) * rsqrtf(var + 1e-5f);
        sc[tid] = s;
        sh[tid] = __ldg(beta2 + tid) - mean * s;
    }
    __syncthreads();
    int i = blockIdx.x * blockDim.x + tid;
    if (i >= n32) return;
    int c = (i & 31) * 4;
    float4 v = ((float4*)out)[i];
    v.x = fmaxf(fmaf(v.x, sc[c + 0], sh[c + 0]), 0.f);
    v.y = fmaxf(fmaf(v.y, sc[c + 1], sh[c + 1]), 0.f);
    v.z = fmaxf(fmaf(v.z, sc[c + 2], sh[c + 2]), 0.f);
    v.w = fmaxf(fmaf(v.w, sc[c + 3], sh[c + 3]), 0.f);
    ((float4*)out)[i] = v;
}

// ======================= launch =======================
extern "C" void kernel_launch(void* const* d_in, const int* in_sizes, int n_in,
                              void* d_out, int out_size) {
    const float* x      = (const float*)d_in[0];
    const void* ei      = d_in[1];
    const float* eps    = (const float*)d_in[2];
    const float* W1     = (const float*)d_in[3];
    const float* b1     = (const float*)d_in[4];
    const float* gamma1 = (const float*)d_in[5];
    const float* beta1  = (const float*)d_in[6];
    const float* W2     = (const float*)d_in[7];
    const float* b2     = (const float*)d_in[8];
    const float* gamma2 = (const float*)d_in[9];
    const float* beta2  = (const float*)d_in[10];
    float* out = (float*)d_out;

    int n   = in_sizes[0] / DF;
    int E   = in_sizes[1] / 2;
    int n32 = n * (DF / 4);
    float invN = 1.f / (float)n;

    const int SMEM = SMEM_FLOATS * 4;  // 100352 bytes
    cudaFuncSetAttribute(gemm_tc<1>, cudaFuncAttributeMaxDynamicSharedMemorySize, SMEM);
    cudaFuncSetAttribute(gemm_tc<2>, cudaFuncAttributeMaxDynamicSharedMemorySize, SMEM);

    int NB = (n32 + 255) / 256;
    fused_init<<<NB + 2, 256>>>(x, eps, W1, W2, (const int*)ei, n32, NB);

    int warps = (E + 3) / 4;
    scatter_kernel<<<(warps * 32 + 255) / 256, 256>>>(x, ei, E, n);

    int gblocks = (n + 127) / 128;
    gemm_tc<1><<<gblocks, 256, SMEM>>>(b1, nullptr, nullptr, nullptr, n, invN);
    gemm_tc<2><<<gblocks, 256, SMEM>>>(b2, gamma1, beta1, out, n, invN);
    apply_kernel<<<(n32 + 255) / 256, 256>>>(out, gamma2, beta2, n32, invN);
}

// round 8
// speedup vs baseline: 1.4735x; 1.0154x over previous
#include <cuda_runtime.h>
#include <cuda_bf16.h>
#include <cstdint>

#define DF 128
#define NMAX 50048

// ======================= scratch (no allocations allowed) =======================
__device__ __align__(128) float g_buf1[NMAX * DF];   // (1+eps)*x + agg
__device__ __align__(128) float g_buf2[NMAX * DF];   // pre-BN layer-1 output
__device__ __align__(128) uint4 g_Bimg[2 * 4096];    // per layer: packed W frags {b0h,b1h,b0l,b1l}
__device__ __align__(128) float g_stats[512];        // [sum1|sq1|sum2|sq2]
__device__ int g_is64;

// ======================= helpers =======================
__device__ __forceinline__ void mma16(float* d, uint4 a, uint32_t b0, uint32_t b1) {
    asm volatile("mma.sync.aligned.m16n8k16.row.col.f32.bf16.bf16.f32 "
                 "{%0,%1,%2,%3},{%4,%5,%6,%7},{%8,%9},{%0,%1,%2,%3};"
                 : "+f"(d[0]), "+f"(d[1]), "+f"(d[2]), "+f"(d[3])
                 : "r"(a.x), "r"(a.y), "r"(a.z), "r"(a.w), "r"(b0), "r"(b1));
}
__device__ __forceinline__ uint32_t pack2(float lo_e, float hi_e) {
    __nv_bfloat162 h = __floats2bfloat162_rn(lo_e, hi_e);  // .x = low half
    return *reinterpret_cast<uint32_t*>(&h);
}

// ======================= fused init: scale x, zero stats, pack W, detect dtype ===
__device__ void prep_w_block(const float* __restrict__ W, uint4* __restrict__ img) {
    for (int idx = threadIdx.x; idx < 16384; idx += 256) {
        int nn = idx >> 7, k = idx & 127;
        float v = __ldg(W + idx);
        __nv_bfloat16 hb = __float2bfloat16(v);
        __nv_bfloat16 lb = __float2bfloat16(v - __bfloat162float(hb));
        int nt = nn >> 3, kstep = k >> 4, kk = k & 15;
        int lane = (nn & 7) * 4 + ((kk & 7) >> 1);
        int reg = (kk >> 3) & 1;
        int half = kk & 1;
        __nv_bfloat16* p = (__nv_bfloat16*)(img + (nt * 8 + kstep) * 32 + lane);
        p[reg * 2 + half] = hb;       // .x/.y words = hi
        p[4 + reg * 2 + half] = lb;   // .z/.w words = lo
    }
}

__global__ void fused_init(const float* __restrict__ x, const float* __restrict__ eps,
                           const float* __restrict__ W1, const float* __restrict__ W2,
                           const int* __restrict__ ei, int n32, int NB) {
    if ((int)blockIdx.x >= NB) {
        int wb = blockIdx.x - NB;
        prep_w_block(wb ? W2 : W1, g_Bimg + wb * 4096);
        if (wb == 0 && threadIdx.x == 0) {
            int allz = 1;
            #pragma unroll
            for (int i = 0; i < 8; i++) if (ei[2 * i + 1] != 0) allz = 0;
            g_is64 = allz;
        }
        return;
    }
    int i = blockIdx.x * blockDim.x + threadIdx.x;
    if (i < 512) g_stats[i] = 0.f;
    if (i < n32) {
        float s = 1.f + __ldg(eps);
        float4 v = __ldg((const float4*)x + i);
        v.x *= s; v.y *= s; v.z *= s; v.w *= s;
        ((float4*)g_buf1)[i] = v;
    }
}

// ======================= scatter: 4 edges/warp, batched loads, v4 reds ==========
__global__ void scatter_kernel(const float* __restrict__ x, const void* __restrict__ eiv,
                               int E, int n) {
    int w = (blockIdx.x * blockDim.x + threadIdx.x) >> 5;
    int lane = threadIdx.x & 31;
    int base = w * 4;
    if (base >= E) return;
    float4 v[4];
    int r[4], ok[4];
    #pragma unroll
    for (int i = 0; i < 4; i++) {
        int e = base + i;
        ok[i] = 0;
        if (e < E) {
            int rr, cc;
            if (g_is64) {
                const long long* ei = (const long long*)eiv;
                rr = (int)__ldg(ei + e);
                cc = (int)__ldg(ei + E + e);
            } else {
                const int* ei = (const int*)eiv;
                rr = __ldg(ei + e);
                cc = __ldg(ei + E + e);
            }
            if ((unsigned)rr < (unsigned)n && (unsigned)cc < (unsigned)n) {
                ok[i] = 1; r[i] = rr;
                v[i] = __ldg((const float4*)(x + (size_t)cc * DF) + lane);
            }
        }
    }
    #pragma unroll
    for (int i = 0; i < 4; i++) {
        if (ok[i]) {
            float* dst = g_buf1 + (size_t)r[i] * DF + lane * 4;
            asm volatile("red.global.add.v4.f32 [%0], {%1,%2,%3,%4};"
                         :: "l"(dst), "f"(v[i].x), "f"(v[i].y), "f"(v[i].z), "f"(v[i].w) : "memory");
        }
    }
}

// ======================= bf16 split-MMA GEMM + BN stats (pipelined) =============
// SMEM floats: sSum[128] | sSq[128] | sBn[256] | sAh[2][2048 u32] | sAl[2][2048 u32] | sB[16384]
#define SM_SUM 0
#define SM_SQ  128
#define SM_BN  256
#define SM_AH  512
#define SM_AL  (512 + 4096)
#define SM_B   (512 + 8192)
#define SMEM_FLOATS (512 + 8192 + 16384)   // 25088 floats = 100352 B

template <int LAYER>
__global__ __launch_bounds__(256, 2) void gemm_tc(const float* __restrict__ bias,
                                                  const float* __restrict__ gamma1,
                                                  const float* __restrict__ beta1,
                                                  float* __restrict__ outParam, int n, float invN) {
    extern __shared__ float smf[];
    uint32_t* sAh = (uint32_t*)(smf + SM_AH);
    uint32_t* sAl = (uint32_t*)(smf + SM_AL);
    const uint4* B4 = (const uint4*)(smf + SM_B);
    const uint4* A4h = (const uint4*)sAh;
    const uint4* A4l = (const uint4*)sAl;
    float* sBn = smf + SM_BN;

    int tid = threadIdx.x, wid = tid >> 5, lane = tid & 31;
    int warpM = wid & 3, warpN = wid >> 2;
    int row0 = blockIdx.x * 128;

    const float* A = (LAYER == 1) ? g_buf1 : g_buf2;
    const uint4* Bimg = g_Bimg + (LAYER == 1 ? 0 : 4096);
    float* Out = (LAYER == 1) ? g_buf2 : outParam;
    float* gSum = g_stats + (LAYER == 1 ? 0 : 256);
    float* gSq  = g_stats + (LAYER == 1 ? 128 : 384);

    if (tid < 128) {
        smf[SM_SUM + tid] = 0.f;
        smf[SM_SQ + tid] = 0.f;
        if (LAYER == 2) {  // fold BN1 finalize into prologue
            float sum = g_stats[tid], sq = g_stats[128 + tid];
            float mean = sum * invN;
            float var = sq * invN - mean * mean;
            float sc = __ldg(gamma1 + tid) * rsqrtf(var + 1e-5f);
            sBn[tid] = sc;
            sBn[128 + tid] = __ldg(beta1 + tid) - mean * sc;
        }
    }
    // stage full B fragment image (4096 uint4)
    {
        uint4* dst = (uint4*)(smf + SM_B);
        #pragma unroll
        for (int i = 0; i < 16; i++) dst[tid + 256 * i] = __ldg(Bimg + tid + 256 * i);
    }
    __syncthreads();   // sBn ready for conversion (and B staging half-done)

    // ---- per-thread chunk load (32 cols = 8 float4) ----
    int mld = tid >> 3;            // row handled by this thread (4 rows total, +32 strided)
    int f4c = tid & 7;             // float4 col within chunk
    auto ldA = [&](int kc, float4* v) {
        #pragma unroll
        for (int i = 0; i < 4; i++) {
            int m = mld + 32 * i;
            int gr = row0 + m;
            v[i] = make_float4(0.f, 0.f, 0.f, 0.f);
            if (gr < n) v[i] = __ldg((const float4*)(A + (size_t)gr * DF) + kc * 8 + f4c);
        }
    };
    auto cvA = [&](int buf, int kc, float4* v) {
        #pragma unroll
        for (int i = 0; i < 4; i++) {
            int m = mld + 32 * i;
            float4 w = v[i];
            if (LAYER == 2) {
                int c = (kc * 8 + f4c) * 4;
                w.x = fmaxf(fmaf(w.x, sBn[c + 0], sBn[128 + c + 0]), 0.f);
                w.y = fmaxf(fmaf(w.y, sBn[c + 1], sBn[128 + c + 1]), 0.f);
                w.z = fmaxf(fmaf(w.z, sBn[c + 2], sBn[128 + c + 2]), 0.f);
                w.w = fmaxf(fmaf(w.w, sBn[c + 3], sBn[128 + c + 3]), 0.f);
            }
            int g = m >> 4, mr = m & 15;
            int kstep = f4c >> 2, f2 = f4c & 3;
            int L0 = (mr & 7) * 4 + (f2 & 1) * 2;
            int r = (((f2 >> 1) & 1) << 1) + (mr >> 3);
            uint32_t h01 = pack2(w.x, w.y);
            uint32_t h23 = pack2(w.z, w.w);
            __nv_bfloat162* hp01 = (__nv_bfloat162*)&h01;
            __nv_bfloat162* hp23 = (__nv_bfloat162*)&h23;
            uint32_t l01 = pack2(w.x - __bfloat162float(hp01->x), w.y - __bfloat162float(hp01->y));
            uint32_t l23 = pack2(w.z - __bfloat162float(hp23->x), w.w - __bfloat162float(hp23->y));
            int base = buf * 2048 + ((g * 2 + kstep) * 32 + L0) * 4 + r;
            sAh[base] = h01;
            sAh[base + 4] = h23;
            sAl[base] = l01;
            sAl[base + 4] = l23;
        }
    };

    float acc[2][8][4];
    #pragma unroll
    for (int mt = 0; mt < 2; mt++)
        #pragma unroll
        for (int nt = 0; nt < 8; nt++)
            #pragma unroll
            for (int j = 0; j < 4; j++) acc[mt][nt][j] = 0.f;

    int g0 = warpM * 2;
    float4 v[4];
    ldA(0, v);
    cvA(0, 0, v);    // chunk0 -> buf0
    ldA(1, v);
    __syncthreads(); // conv0 + B ready

    #pragma unroll
    for (int kc = 0; kc < 4; kc++) {
        // overlap: convert chunk kc+1 (other warps' MMAs run meanwhile), prefetch kc+2
        if (kc < 3) {
            cvA((kc + 1) & 1, kc + 1, v);
            if (kc < 2) ldA(kc + 2, v);
        }
        // MMA chunk kc from buf kc&1
        int bofs = (kc & 1) * 512;  // uint4 offset
        #pragma unroll
        for (int kk = 0; kk < 2; kk++) {
            int ksG = kc * 2 + kk;
            uint4 ah0 = A4h[bofs + (g0 * 2 + kk) * 32 + lane];
            uint4 al0 = A4l[bofs + (g0 * 2 + kk) * 32 + lane];
            uint4 ah1 = A4h[bofs + ((g0 + 1) * 2 + kk) * 32 + lane];
            uint4 al1 = A4l[bofs + ((g0 + 1) * 2 + kk) * 32 + lane];
            #pragma unroll
            for (int h = 0; h < 2; h++) {
                uint4 b0 = B4[((warpN * 8 + h * 4 + 0) * 8 + ksG) * 32 + lane];
                uint4 b1 = B4[((warpN * 8 + h * 4 + 1) * 8 + ksG) * 32 + lane];
                uint4 b2 = B4[((warpN * 8 + h * 4 + 2) * 8 + ksG) * 32 + lane];
                uint4 b3 = B4[((warpN * 8 + h * 4 + 3) * 8 + ksG) * 32 + lane];
                int nb = h * 4;
                // product-major: 8 independent MMAs between accumulator reuses
                mma16(acc[0][nb + 0], ah0, b0.x, b0.y);
                mma16(acc[0][nb + 1], ah0, b1.x, b1.y);
                mma16(acc[0][nb + 2], ah0, b2.x, b2.y);
                mma16(acc[0][nb + 3], ah0, b3.x, b3.y);
                mma16(acc[1][nb + 0], ah1, b0.x, b0.y);
                mma16(acc[1][nb + 1], ah1, b1.x, b1.y);
                mma16(acc[1][nb + 2], ah1, b2.x, b2.y);
                mma16(acc[1][nb + 3], ah1, b3.x, b3.y);
                mma16(acc[0][nb + 0], al0, b0.x, b0.y);
                mma16(acc[0][nb + 1], al0, b1.x, b1.y);
                mma16(acc[0][nb + 2], al0, b2.x, b2.y);
                mma16(acc[0][nb + 3], al0, b3.x, b3.y);
                mma16(acc[1][nb + 0], al1, b0.x, b0.y);
                mma16(acc[1][nb + 1], al1, b1.x, b1.y);
                mma16(acc[1][nb + 2], al1, b2.x, b2.y);
                mma16(acc[1][nb + 3], al1, b3.x, b3.y);
                mma16(acc[0][nb + 0], ah0, b0.z, b0.w);
                mma16(acc[0][nb + 1], ah0, b1.z, b1.w);
                mma16(acc[0][nb + 2], ah0, b2.z, b2.w);
                mma16(acc[0][nb + 3], ah0, b3.z, b3.w);
                mma16(acc[1][nb + 0], ah1, b0.z, b0.w);
                mma16(acc[1][nb + 1], ah1, b1.z, b1.w);
                mma16(acc[1][nb + 2], ah1, b2.z, b2.w);
                mma16(acc[1][nb + 3], ah1, b3.z, b3.w);
            }
        }
        __syncthreads();
    }

    // ---------------- epilogue: bias, store, BN stats ----------------
    float cs[16], cq[16];
    #pragma unroll
    for (int j = 0; j < 16; j++) { cs[j] = 0.f; cq[j] = 0.f; }

    int rbase = row0 + warpM * 32 + (lane >> 2);
    #pragma unroll
    for (int nt = 0; nt < 8; nt++) {
        int C = warpN * 64 + nt * 8 + (lane & 3) * 2;
        float2 bb = __ldg((const float2*)(bias + C));
        #pragma unroll
        for (int mt = 0; mt < 2; mt++) {
            int R0 = rbase + mt * 16;
            int R1 = R0 + 8;
            float v00 = acc[mt][nt][0] + bb.x;
            float v01 = acc[mt][nt][1] + bb.y;
            float v10 = acc[mt][nt][2] + bb.x;
            float v11 = acc[mt][nt][3] + bb.y;
            if (R0 < n) {
                *(float2*)(Out + (size_t)R0 * DF + C) = make_float2(v00, v01);
                cs[nt * 2] += v00;     cq[nt * 2] += v00 * v00;
                cs[nt * 2 + 1] += v01; cq[nt * 2 + 1] += v01 * v01;
            }
            if (R1 < n) {
                *(float2*)(Out + (size_t)R1 * DF + C) = make_float2(v10, v11);
                cs[nt * 2] += v10;     cq[nt * 2] += v10 * v10;
                cs[nt * 2 + 1] += v11; cq[nt * 2 + 1] += v11 * v11;
            }
        }
    }
    #pragma unroll
    for (int off = 4; off < 32; off <<= 1) {
        #pragma unroll
        for (int j = 0; j < 16; j++) {
            cs[j] += __shfl_xor_sync(0xFFFFFFFF, cs[j], off);
            cq[j] += __shfl_xor_sync(0xFFFFFFFF, cq[j], off);
        }
    }
    if (lane < 4) {
        #pragma unroll
        for (int nt = 0; nt < 8; nt++) {
            int C = warpN * 64 + nt * 8 + lane * 2;
            atomicAdd(&smf[SM_SUM + C], cs[nt * 2]);
            atomicAdd(&smf[SM_SUM + C + 1], cs[nt * 2 + 1]);
            atomicAdd(&smf[SM_SQ + C], cq[nt * 2]);
            atomicAdd(&smf[SM_SQ + C + 1], cq[nt * 2 + 1]);
        }
    }
    __syncthreads();
    if (tid < 128) {
        atomicAdd(&gSum[tid], smf[SM_SUM + tid]);
        atomicAdd(&gSq[tid],  smf[SM_SQ + tid]);
    }
}

// ======================= final BN2 + ReLU (finalize fused per-block) ===========
__global__ void apply_kernel(float* __restrict__ out, const float* __restrict__ gamma2,
                             const float* __restrict__ beta2, int n32, float invN) {
    __shared__ float sc[128], sh[128];
    int tid = threadIdx.x;
    if (tid < 128) {
        float sum = g_stats[256 + tid], sq = g_stats[384 + tid];
        float mean = sum * invN;
        float var = sq * invN - mean * mean;
        float s = __ldg(gamma2 + tid) * rsqrtf(var + 1e-5f);
        sc[tid] = s;
        sh[tid] = __ldg(beta2 + tid) - mean * s;
    }
    __syncthreads();
    int i = blockIdx.x * blockDim.x + tid;
    if (i >= n32) return;
    int c = (i & 31) * 4;
    float4 v = ((float4*)out)[i];
    v.x = fmaxf(fmaf(v.x, sc[c + 0], sh[c + 0]), 0.f);
    v.y = fmaxf(fmaf(v.y, sc[c + 1], sh[c + 1]), 0.f);
    v.z = fmaxf(fmaf(v.z, sc[c + 2], sh[c + 2]), 0.f);
    v.w = fmaxf(fmaf(v.w, sc[c + 3], sh[c + 3]), 0.f);
    ((float4*)out)[i] = v;
}

// ======================= launch =======================
extern "C" void kernel_launch(void* const* d_in, const int* in_sizes, int n_in,
                              void* d_out, int out_size) {
    const float* x      = (const float*)d_in[0];
    const void* ei      = d_in[1];
    const float* eps    = (const float*)d_in[2];
    const float* W1     = (const float*)d_in[3];
    const float* b1     = (const float*)d_in[4];
    const float* gamma1 = (const float*)d_in[5];
    const float* beta1  = (const float*)d_in[6];
    const float* W2     = (const float*)d_in[7];
    const float* b2     = (const float*)d_in[8];
    const float* gamma2 = (const float*)d_in[9];
    const float* beta2  = (const float*)d_in[10];
    float* out = (float*)d_out;

    int n   = in_sizes[0] / DF;
    int E   = in_sizes[1] / 2;
    int n32 = n * (DF / 4);
    float invN = 1.f / (float)n;

    const int SMEM = SMEM_FLOATS * 4;  // 100352 bytes
    cudaFuncSetAttribute(gemm_tc<1>, cudaFuncAttributeMaxDynamicSharedMemorySize, SMEM);
    cudaFuncSetAttribute(gemm_tc<2>, cudaFuncAttributeMaxDynamicSharedMemorySize, SMEM);

    int NB = (n32 + 255) / 256;
    fused_init<<<NB + 2, 256>>>(x, eps, W1, W2, (const int*)ei, n32, NB);

    int warps = (E + 3) / 4;
    scatter_kernel<<<(warps * 32 + 255) / 256, 256>>>(x, ei, E, n);

    int gblocks = (n + 127) / 128;
    gemm_tc<1><<<gblocks, 256, SMEM>>>(b1, nullptr, nullptr, nullptr, n, invN);
    gemm_tc<2><<<gblocks, 256, SMEM>>>(b2, gamma1, beta1, out, n, invN);
    apply_kernel<<<(n32 + 255) / 256, 256>>>(out, gamma2, beta2, n32, invN);
}

// round 9
// speedup vs baseline: 1.7290x; 1.1734x over previous
#include <cuda_runtime.h>
#include <cuda_bf16.h>
#include <cstdint>

#define DF 128
#define NMAX 50048
#define EMAX 1000000

// ======================= scratch (no allocations allowed) =======================
__device__ __align__(128) float g_buf1[NMAX * DF];   // (1+eps)*x + agg
__device__ __align__(128) float g_buf2[NMAX * DF];   // pre-BN layer-1 output
__device__ __align__(128) uint4 g_Bimg[2 * 4096];    // per layer: packed W frags {b0h,b1h,b0l,b1l}
__device__ __align__(128) float g_stats[512];        // [sum1|sq1|sum2|sq2]
__device__ __align__(128) int g_cnt[NMAX];           // per-row degree counts
__device__ __align__(128) int g_rowptr[NMAX + 1];    // CSR row pointers
__device__ __align__(128) int g_pos[NMAX];           // fill cursors
__device__ __align__(128) int g_col[EMAX];           // CSR column indices
__device__ __align__(128) int g_bsum[256];           // block sums for scan
__device__ __align__(128) int g_boff[256];           // block offsets (exclusive)
__device__ int g_is64;

// ======================= helpers =======================
__device__ __forceinline__ void mma16(float* d, uint4 a, uint32_t b0, uint32_t b1) {
    asm volatile("mma.sync.aligned.m16n8k16.row.col.f32.bf16.bf16.f32 "
                 "{%0,%1,%2,%3},{%4,%5,%6,%7},{%8,%9},{%0,%1,%2,%3};"
                 : "+f"(d[0]), "+f"(d[1]), "+f"(d[2]), "+f"(d[3])
                 : "r"(a.x), "r"(a.y), "r"(a.z), "r"(a.w), "r"(b0), "r"(b1));
}
__device__ __forceinline__ uint32_t pack2(float lo_e, float hi_e) {
    __nv_bfloat162 h = __floats2bfloat162_rn(lo_e, hi_e);  // .x = low half
    return *reinterpret_cast<uint32_t*>(&h);
}
__device__ __forceinline__ void read_edge(const void* eiv, int e, int E, int& r, int& c) {
    if (g_is64) {
        const long long* ei = (const long long*)eiv;
        r = (int)__ldg(ei + e);
        c = (int)__ldg(ei + E + e);
    } else {
        const int* ei = (const int*)eiv;
        r = __ldg(ei + e);
        c = __ldg(ei + E + e);
    }
}

// ======================= prep0: zero counters/stats, pack W, detect dtype =======
__device__ void prep_w_block(const float* __restrict__ W, uint4* __restrict__ img) {
    for (int idx = threadIdx.x; idx < 16384; idx += 256) {
        int nn = idx >> 7, k = idx & 127;
        float v = __ldg(W + idx);
        __nv_bfloat16 hb = __float2bfloat16(v);
        __nv_bfloat16 lb = __float2bfloat16(v - __bfloat162float(hb));
        int nt = nn >> 3, kstep = k >> 4, kk = k & 15;
        int lane = (nn & 7) * 4 + ((kk & 7) >> 1);
        int reg = (kk >> 3) & 1;
        int half = kk & 1;
        __nv_bfloat16* p = (__nv_bfloat16*)(img + (nt * 8 + kstep) * 32 + lane);
        p[reg * 2 + half] = hb;       // .x/.y words = hi
        p[4 + reg * 2 + half] = lb;   // .z/.w words = lo
    }
}

__global__ void prep0(const float* __restrict__ W1, const float* __restrict__ W2,
                      const int* __restrict__ ei, int n, int NBZ) {
    int b = blockIdx.x;
    if (b < NBZ) {
        int i = b * 256 + threadIdx.x;
        if (i < n) g_cnt[i] = 0;
        if (i < 512) g_stats[i] = 0.f;
        return;
    }
    int wb = b - NBZ;  // 0 or 1
    prep_w_block(wb ? W2 : W1, g_Bimg + wb * 4096);
    if (wb == 0 && threadIdx.x == 0) {
        int allz = 1;
        #pragma unroll
        for (int i = 0; i < 8; i++) if (ei[2 * i + 1] != 0) allz = 0;
        g_is64 = allz;
    }
}

// ======================= CSR build =======================
__global__ void hist_kernel(const void* __restrict__ eiv, int E, int n) {
    int e = blockIdx.x * blockDim.x + threadIdx.x;
    if (e >= E) return;
    int r, c;
    read_edge(eiv, e, E, r, c);
    if ((unsigned)r < (unsigned)n && (unsigned)c < (unsigned)n)
        atomicAdd(&g_cnt[r], 1);
}

__global__ void scanA(int n) {  // block sums
    __shared__ int sm[256];
    int i = blockIdx.x * 256 + threadIdx.x;
    int v = (i < n) ? g_cnt[i] : 0;
    sm[threadIdx.x] = v;
    __syncthreads();
    #pragma unroll
    for (int s = 128; s > 0; s >>= 1) {
        if (threadIdx.x < s) sm[threadIdx.x] += sm[threadIdx.x + s];
        __syncthreads();
    }
    if (threadIdx.x == 0) g_bsum[blockIdx.x] = sm[0];
}

__global__ void scanB(int NB) {  // exclusive scan of block sums (NB <= 256)
    __shared__ int sm[256];
    int t = threadIdx.x;
    int v = (t < NB) ? g_bsum[t] : 0;
    sm[t] = v;
    __syncthreads();
    #pragma unroll
    for (int off = 1; off < 256; off <<= 1) {
        int add = (t >= off) ? sm[t - off] : 0;
        __syncthreads();
        sm[t] += add;
        __syncthreads();
    }
    if (t < NB) g_boff[t] = sm[t] - v;  // exclusive
}

__global__ void scanC(int n) {  // rowptr + cursors
    __shared__ int sm[256];
    int t = threadIdx.x;
    int i = blockIdx.x * 256 + t;
    int v = (i < n) ? g_cnt[i] : 0;
    sm[t] = v;
    __syncthreads();
    #pragma unroll
    for (int off = 1; off < 256; off <<= 1) {
        int add = (t >= off) ? sm[t - off] : 0;
        __syncthreads();
        sm[t] += add;
        __syncthreads();
    }
    int base = g_boff[blockIdx.x];
    int excl = base + sm[t] - v;
    if (i < n) {
        g_rowptr[i] = excl;
        g_pos[i] = excl;
        if (i == n - 1) g_rowptr[n] = excl + v;
    }
}

__global__ void fill_kernel(const void* __restrict__ eiv, int E, int n) {
    int e = blockIdx.x * blockDim.x + threadIdx.x;
    if (e >= E) return;
    int r, c;
    read_edge(eiv, e, E, r, c);
    if ((unsigned)r < (unsigned)n && (unsigned)c < (unsigned)n) {
        int p = atomicAdd(&g_pos[r], 1);
        if (p < EMAX) g_col[p] = c;
    }
}

// ======================= gather: warp per node, no atomics ======================
// g_buf1[v] = (1+eps)*x[v] + sum_{c in N(v)} x[c]
__global__ void gather_kernel(const float* __restrict__ x, const float* __restrict__ eps, int n) {
    int w = (blockIdx.x * blockDim.x + threadIdx.x) >> 5;
    int lane = threadIdx.x & 31;
    if (w >= n) return;
    const float4* xb = (const float4*)x;
    float s = 1.f + __ldg(eps);
    float4 a = __ldg(xb + (size_t)w * 32 + lane);
    a.x *= s; a.y *= s; a.z *= s; a.w *= s;
    int j = g_rowptr[w], e = g_rowptr[w + 1];
    for (; j + 4 <= e; j += 4) {
        int c0 = __ldg(g_col + j);
        int c1 = __ldg(g_col + j + 1);
        int c2 = __ldg(g_col + j + 2);
        int c3 = __ldg(g_col + j + 3);
        float4 t0 = __ldg(xb + (size_t)c0 * 32 + lane);
        float4 t1 = __ldg(xb + (size_t)c1 * 32 + lane);
        float4 t2 = __ldg(xb + (size_t)c2 * 32 + lane);
        float4 t3 = __ldg(xb + (size_t)c3 * 32 + lane);
        a.x += t0.x + t1.x + t2.x + t3.x;
        a.y += t0.y + t1.y + t2.y + t3.y;
        a.z += t0.z + t1.z + t2.z + t3.z;
        a.w += t0.w + t1.w + t2.w + t3.w;
    }
    for (; j < e; j++) {
        int c = __ldg(g_col + j);
        float4 t = __ldg(xb + (size_t)c * 32 + lane);
        a.x += t.x; a.y += t.y; a.z += t.z; a.w += t.w;
    }
    ((float4*)g_buf1)[(size_t)w * 32 + lane] = a;
}

// ======================= bf16 split-MMA GEMM + BN stats (pipelined) =============
#define SM_SUM 0
#define SM_SQ  128
#define SM_BN  256
#define SM_AH  512
#define SM_AL  (512 + 4096)
#define SM_B   (512 + 8192)
#define SMEM_FLOATS (512 + 8192 + 16384)   // 25088 floats = 100352 B

template <int LAYER>
__global__ __launch_bounds__(256, 2) void gemm_tc(const float* __restrict__ bias,
                                                  const float* __restrict__ gamma1,
                                                  const float* __restrict__ beta1,
                                                  float* __restrict__ outParam, int n, float invN) {
    extern __shared__ float smf[];
    uint32_t* sAh = (uint32_t*)(smf + SM_AH);
    uint32_t* sAl = (uint32_t*)(smf + SM_AL);
    const uint4* B4 = (const uint4*)(smf + SM_B);
    const uint4* A4h = (const uint4*)sAh;
    const uint4* A4l = (const uint4*)sAl;
    float* sBn = smf + SM_BN;

    int tid = threadIdx.x, wid = tid >> 5, lane = tid & 31;
    int warpM = wid & 3, warpN = wid >> 2;
    int row0 = blockIdx.x * 128;

    const float* A = (LAYER == 1) ? g_buf1 : g_buf2;
    const uint4* Bimg = g_Bimg + (LAYER == 1 ? 0 : 4096);
    float* Out = (LAYER == 1) ? g_buf2 : outParam;
    float* gSum = g_stats + (LAYER == 1 ? 0 : 256);
    float* gSq  = g_stats + (LAYER == 1 ? 128 : 384);

    if (tid < 128) {
        smf[SM_SUM + tid] = 0.f;
        smf[SM_SQ + tid] = 0.f;
        if (LAYER == 2) {  // fold BN1 finalize into prologue
            float sum = g_stats[tid], sq = g_stats[128 + tid];
            float mean = sum * invN;
            float var = sq * invN - mean * mean;
            float sc = __ldg(gamma1 + tid) * rsqrtf(var + 1e-5f);
            sBn[tid] = sc;
            sBn[128 + tid] = __ldg(beta1 + tid) - mean * sc;
        }
    }
    {
        uint4* dst = (uint4*)(smf + SM_B);
        #pragma unroll
        for (int i = 0; i < 16; i++) dst[tid + 256 * i] = __ldg(Bimg + tid + 256 * i);
    }
    __syncthreads();

    int mld = tid >> 3;
    int f4c = tid & 7;
    auto ldA = [&](int kc, float4* v) {
        #pragma unroll
        for (int i = 0; i < 4; i++) {
            int m = mld + 32 * i;
            int gr = row0 + m;
            v[i] = make_float4(0.f, 0.f, 0.f, 0.f);
            if (gr < n) v[i] = __ldg((const float4*)(A + (size_t)gr * DF) + kc * 8 + f4c);
        }
    };
    auto cvA = [&](int buf, int kc, float4* v) {
        #pragma unroll
        for (int i = 0; i < 4; i++) {
            int m = mld + 32 * i;
            float4 w = v[i];
            if (LAYER == 2) {
                int c = (kc * 8 + f4c) * 4;
                w.x = fmaxf(fmaf(w.x, sBn[c + 0], sBn[128 + c + 0]), 0.f);
                w.y = fmaxf(fmaf(w.y, sBn[c + 1], sBn[128 + c + 1]), 0.f);
                w.z = fmaxf(fmaf(w.z, sBn[c + 2], sBn[128 + c + 2]), 0.f);
                w.w = fmaxf(fmaf(w.w, sBn[c + 3], sBn[128 + c + 3]), 0.f);
            }
            int g = m >> 4, mr = m & 15;
            int kstep = f4c >> 2, f2 = f4c & 3;
            int L0 = (mr & 7) * 4 + (f2 & 1) * 2;
            int r = (((f2 >> 1) & 1) << 1) + (mr >> 3);
            uint32_t h01 = pack2(w.x, w.y);
            uint32_t h23 = pack2(w.z, w.w);
            __nv_bfloat162* hp01 = (__nv_bfloat162*)&h01;
            __nv_bfloat162* hp23 = (__nv_bfloat162*)&h23;
            uint32_t l01 = pack2(w.x - __bfloat162float(hp01->x), w.y - __bfloat162float(hp01->y));
            uint32_t l23 = pack2(w.z - __bfloat162float(hp23->x), w.w - __bfloat162float(hp23->y));
            int base = buf * 2048 + ((g * 2 + kstep) * 32 + L0) * 4 + r;
            sAh[base] = h01;
            sAh[base + 4] = h23;
            sAl[base] = l01;
            sAl[base + 4] = l23;
        }
    };

    float acc[2][8][4];
    #pragma unroll
    for (int mt = 0; mt < 2; mt++)
        #pragma unroll
        for (int nt = 0; nt < 8; nt++)
            #pragma unroll
            for (int j = 0; j < 4; j++) acc[mt][nt][j] = 0.f;

    int g0 = warpM * 2;
    float4 v[4];
    ldA(0, v);
    cvA(0, 0, v);
    ldA(1, v);
    __syncthreads();

    #pragma unroll
    for (int kc = 0; kc < 4; kc++) {
        if (kc < 3) {
            cvA((kc + 1) & 1, kc + 1, v);
            if (kc < 2) ldA(kc + 2, v);
        }
        int bofs = (kc & 1) * 512;
        #pragma unroll
        for (int kk = 0; kk < 2; kk++) {
            int ksG = kc * 2 + kk;
            uint4 ah0 = A4h[bofs + (g0 * 2 + kk) * 32 + lane];
            uint4 al0 = A4l[bofs + (g0 * 2 + kk) * 32 + lane];
            uint4 ah1 = A4h[bofs + ((g0 + 1) * 2 + kk) * 32 + lane];
            uint4 al1 = A4l[bofs + ((g0 + 1) * 2 + kk) * 32 + lane];
            #pragma unroll
            for (int h = 0; h < 2; h++) {
                uint4 b0 = B4[((warpN * 8 + h * 4 + 0) * 8 + ksG) * 32 + lane];
                uint4 b1 = B4[((warpN * 8 + h * 4 + 1) * 8 + ksG) * 32 + lane];
                uint4 b2 = B4[((warpN * 8 + h * 4 + 2) * 8 + ksG) * 32 + lane];
                uint4 b3 = B4[((warpN * 8 + h * 4 + 3) * 8 + ksG) * 32 + lane];
                int nb = h * 4;
                mma16(acc[0][nb + 0], ah0, b0.x, b0.y);
                mma16(acc[0][nb + 1], ah0, b1.x, b1.y);
                mma16(acc[0][nb + 2], ah0, b2.x, b2.y);
                mma16(acc[0][nb + 3], ah0, b3.x, b3.y);
                mma16(acc[1][nb + 0], ah1, b0.x, b0.y);
                mma16(acc[1][nb + 1], ah1, b1.x, b1.y);
                mma16(acc[1][nb + 2], ah1, b2.x, b2.y);
                mma16(acc[1][nb + 3], ah1, b3.x, b3.y);
                mma16(acc[0][nb + 0], al0, b0.x, b0.y);
                mma16(acc[0][nb + 1], al0, b1.x, b1.y);
                mma16(acc[0][nb + 2], al0, b2.x, b2.y);
                mma16(acc[0][nb + 3], al0, b3.x, b3.y);
                mma16(acc[1][nb + 0], al1, b0.x, b0.y);
                mma16(acc[1][nb + 1], al1, b1.x, b1.y);
                mma16(acc[1][nb + 2], al1, b2.x, b2.y);
                mma16(acc[1][nb + 3], al1, b3.x, b3.y);
                mma16(acc[0][nb + 0], ah0, b0.z, b0.w);
                mma16(acc[0][nb + 1], ah0, b1.z, b1.w);
                mma16(acc[0][nb + 2], ah0, b2.z, b2.w);
                mma16(acc[0][nb + 3], ah0, b3.z, b3.w);
                mma16(acc[1][nb + 0], ah1, b0.z, b0.w);
                mma16(acc[1][nb + 1], ah1, b1.z, b1.w);
                mma16(acc[1][nb + 2], ah1, b2.z, b2.w);
                mma16(acc[1][nb + 3], ah1, b3.z, b3.w);
            }
        }
        __syncthreads();
    }

    // ---------------- epilogue: bias, store, BN stats ----------------
    float cs[16], cq[16];
    #pragma unroll
    for (int j = 0; j < 16; j++) { cs[j] = 0.f; cq[j] = 0.f; }

    int rbase = row0 + warpM * 32 + (lane >> 2);
    #pragma unroll
    for (int nt = 0; nt < 8; nt++) {
        int C = warpN * 64 + nt * 8 + (lane & 3) * 2;
        float2 bb = __ldg((const float2*)(bias + C));
        #pragma unroll
        for (int mt = 0; mt < 2; mt++) {
            int R0 = rbase + mt * 16;
            int R1 = R0 + 8;
            float v00 = acc[mt][nt][0] + bb.x;
            float v01 = acc[mt][nt][1] + bb.y;
            float v10 = acc[mt][nt][2] + bb.x;
            float v11 = acc[mt][nt][3] + bb.y;
            if (R0 < n) {
                *(float2*)(Out + (size_t)R0 * DF + C) = make_float2(v00, v01);
                cs[nt * 2] += v00;     cq[nt * 2] += v00 * v00;
                cs[nt * 2 + 1] += v01; cq[nt * 2 + 1] += v01 * v01;
            }
            if (R1 < n) {
                *(float2*)(Out + (size_t)R1 * DF + C) = make_float2(v10, v11);
                cs[nt * 2] += v10;     cq[nt * 2] += v10 * v10;
                cs[nt * 2 + 1] += v11; cq[nt * 2 + 1] += v11 * v11;
            }
        }
    }
    #pragma unroll
    for (int off = 4; off < 32; off <<= 1) {
        #pragma unroll
        for (int j = 0; j < 16; j++) {
            cs[j] += __shfl_xor_sync(0xFFFFFFFF, cs[j], off);
            cq[j] += __shfl_xor_sync(0xFFFFFFFF, cq[j], off);
        }
    }
    if (lane < 4) {
        #pragma unroll
        for (int nt = 0; nt < 8; nt++) {
            int C = warpN * 64 + nt * 8 + lane * 2;
            atomicAdd(&smf[SM_SUM + C], cs[nt * 2]);
            atomicAdd(&smf[SM_SUM + C + 1], cs[nt * 2 + 1]);
            atomicAdd(&smf[SM_SQ + C], cq[nt * 2]);
            atomicAdd(&smf[SM_SQ + C + 1], cq[nt * 2 + 1]);
        }
    }
    __syncthreads();
    if (tid < 128) {
        atomicAdd(&gSum[tid], smf[SM_SUM + tid]);
        atomicAdd(&gSq[tid],  smf[SM_SQ + tid]);
    }
}

// ======================= final BN2 + ReLU (finalize fused per-block) ===========
__global__ void apply_kernel(float* __restrict__ out, const float* __restrict__ gamma2,
                             const float* __restrict__ beta2, int n32, float invN) {
    __shared__ float sc[128], sh[128];
    int tid = threadIdx.x;
    if (tid < 128) {
        float sum = g_stats[256 + tid], sq = g_stats[384 + tid];
        float mean = sum * invN;
        float var = sq * invN - mean * mean;
        float s = __ldg(gamma2 + tid) * rsqrtf(var + 1e-5f);
        sc[tid] = s;
        sh[tid] = __ldg(beta2 + tid) - mean * s;
    }
    __syncthreads();
    int i = blockIdx.x * blockDim.x + tid;
    if (i >= n32) return;
    int c = (i & 31) * 4;
    float4 v = ((float4*)out)[i];
    v.x = fmaxf(fmaf(v.x, sc[c + 0], sh[c + 0]), 0.f);
    v.y = fmaxf(fmaf(v.y, sc[c + 1], sh[c + 1]), 0.f);
    v.z = fmaxf(fmaf(v.z, sc[c + 2], sh[c + 2]), 0.f);
    v.w = fmaxf(fmaf(v.w, sc[c + 3], sh[c + 3]), 0.f);
    ((float4*)out)[i] = v;
}

// ======================= launch =======================
extern "C" void kernel_launch(void* const* d_in, const int* in_sizes, int n_in,
                              void* d_out, int out_size) {
    const float* x      = (const float*)d_in[0];
    const void* ei      = d_in[1];
    const float* eps    = (const float*)d_in[2];
    const float* W1     = (const float*)d_in[3];
    const float* b1     = (const float*)d_in[4];
    const float* gamma1 = (const float*)d_in[5];
    const float* beta1  = (const float*)d_in[6];
    const float* W2     = (const float*)d_in[7];
    const float* b2     = (const float*)d_in[8];
    const float* gamma2 = (const float*)d_in[9];
    const float* beta2  = (const float*)d_in[10];
    float* out = (float*)d_out;

    int n   = in_sizes[0] / DF;
    int E   = in_sizes[1] / 2;
    int n32 = n * (DF / 4);
    float invN = 1.f / (float)n;

    const int SMEM = SMEM_FLOATS * 4;  // 100352 bytes
    cudaFuncSetAttribute(gemm_tc<1>, cudaFuncAttributeMaxDynamicSharedMemorySize, SMEM);
    cudaFuncSetAttribute(gemm_tc<2>, cudaFuncAttributeMaxDynamicSharedMemorySize, SMEM);

    int NBZ = (n + 255) / 256;
    int EB = (E + 255) / 256;

    prep0<<<NBZ + 2, 256>>>(W1, W2, (const int*)ei, n, NBZ);
    hist_kernel<<<EB, 256>>>(ei, E, n);
    scanA<<<NBZ, 256>>>(n);
    scanB<<<1, 256>>>(NBZ);
    scanC<<<NBZ, 256>>>(n);
    fill_kernel<<<EB, 256>>>(ei, E, n);
    gather_kernel<<<(n * 32 + 255) / 256, 256>>>(x, eps, n);

    int gblocks = (n + 127) / 128;
    gemm_tc<1><<<gblocks, 256, SMEM>>>(b1, nullptr, nullptr, nullptr, n, invN);
    gemm_tc<2><<<gblocks, 256, SMEM>>>(b2, gamma1, beta1, out, n, invN);
    apply_kernel<<<(n32 + 255) / 256, 256>>>(out, gamma2, beta2, n32, invN);
}

// round 11
// speedup vs baseline: 1.7777x; 1.0282x over previous
#include <cuda_runtime.h>
#include <cuda_bf16.h>
#include <cstdint>

#define DF 128
#define NMAX 50048
#define EMAX 1000000

// ======================= scratch (no allocations allowed) =======================
__device__ __align__(128) float g_buf1[NMAX * DF];   // (1+eps)*x + agg
__device__ __align__(128) float g_buf2[NMAX * DF];   // pre-BN layer-1 output
__device__ __align__(128) uint4 g_Bimg[2 * 4096];    // per layer: packed W frags {b0h,b1h,b0l,b1l}
__device__ __align__(128) float g_stats[512];        // [sum1|sq1|sum2|sq2]
__device__ __align__(128) int g_cnt[NMAX];           // per-row degree counts
__device__ __align__(128) int g_rs[NMAX];            // segment start
__device__ __align__(128) int g_re[NMAX];            // segment end
__device__ __align__(128) int g_pos[NMAX];           // fill cursors
__device__ __align__(128) int g_col[EMAX];           // column indices (segmented, order-free)
__device__ int g_total;                              // global segment allocator
__device__ int g_is64;

// ======================= helpers =======================
__device__ __forceinline__ void mma16(float* d, uint4 a, uint32_t b0, uint32_t b1) {
    asm volatile("mma.sync.aligned.m16n8k16.row.col.f32.bf16.bf16.f32 "
                 "{%0,%1,%2,%3},{%4,%5,%6,%7},{%8,%9},{%0,%1,%2,%3};"
                 : "+f"(d[0]), "+f"(d[1]), "+f"(d[2]), "+f"(d[3])
                 : "r"(a.x), "r"(a.y), "r"(a.z), "r"(a.w), "r"(b0), "r"(b1));
}
__device__ __forceinline__ uint32_t pack2(float lo_e, float hi_e) {
    __nv_bfloat162 h = __floats2bfloat162_rn(lo_e, hi_e);  // .x = low half
    return *reinterpret_cast<uint32_t*>(&h);
}
__device__ __forceinline__ void read_edge(const void* eiv, int e, int E, int& r, int& c) {
    if (g_is64) {
        const long long* ei = (const long long*)eiv;
        r = (int)__ldg(ei + e);
        c = (int)__ldg(ei + E + e);
    } else {
        const int* ei = (const int*)eiv;
        r = __ldg(ei + e);
        c = __ldg(ei + E + e);
    }
}

// ======================= prep0: zero counters/stats, pack W, detect dtype =======
__device__ void prep_w_block(const float* __restrict__ W, uint4* __restrict__ img) {
    for (int idx = threadIdx.x; idx < 16384; idx += 256) {
        int nn = idx >> 7, k = idx & 127;
        float v = __ldg(W + idx);
        __nv_bfloat16 hb = __float2bfloat16(v);
        __nv_bfloat16 lb = __float2bfloat16(v - __bfloat162float(hb));
        int nt = nn >> 3, kstep = k >> 4, kk = k & 15;
        int lane = (nn & 7) * 4 + ((kk & 7) >> 1);
        int reg = (kk >> 3) & 1;
        int half = kk & 1;
        __nv_bfloat16* p = (__nv_bfloat16*)(img + (nt * 8 + kstep) * 32 + lane);
        p[reg * 2 + half] = hb;       // .x/.y words = hi
        p[4 + reg * 2 + half] = lb;   // .z/.w words = lo
    }
}

__global__ void prep0(const float* __restrict__ W1, const float* __restrict__ W2,
                      const int* __restrict__ ei, int n, int NBZ) {
    int b = blockIdx.x;
    if (b < NBZ) {
        int i = b * 256 + threadIdx.x;
        if (i < n) g_cnt[i] = 0;
        if (i < 512) g_stats[i] = 0.f;
        if (b == 0 && threadIdx.x == 0) g_total = 0;
        return;
    }
    int wb = b - NBZ;  // 0 or 1
    prep_w_block(wb ? W2 : W1, g_Bimg + wb * 4096);
    if (wb == 0 && threadIdx.x == 0) {
        int allz = 1;
        #pragma unroll
        for (int i = 0; i < 8; i++) if (ei[2 * i + 1] != 0) allz = 0;
        g_is64 = allz;
    }
}

// ======================= CSR-ish build (order-free segments) ====================
__global__ void hist_kernel(const void* __restrict__ eiv, int E, int n) {
    int e = blockIdx.x * blockDim.x + threadIdx.x;
    if (e >= E) return;
    int r, c;
    read_edge(eiv, e, E, r, c);
    if ((unsigned)r < (unsigned)n && (unsigned)c < (unsigned)n)
        atomicAdd(&g_cnt[r], 1);
}

// one kernel replaces scanA/scanB/scanC: block-local scan + 1 global atomic/block
__global__ void offsets_kernel(int n) {
    __shared__ int sm[256];
    __shared__ int blockBase;
    int t = threadIdx.x;
    int i = blockIdx.x * 256 + t;
    int cnt = (i < n) ? g_cnt[i] : 0;
    sm[t] = cnt;
    __syncthreads();
    #pragma unroll
    for (int off = 1; off < 256; off <<= 1) {
        int add = (t >= off) ? sm[t - off] : 0;
        __syncthreads();
        sm[t] += add;
        __syncthreads();
    }
    if (t == 255) blockBase = atomicAdd(&g_total, sm[255]);
    __syncthreads();
    if (i < n) {
        int start = blockBase + sm[t] - cnt;
        g_rs[i] = start;
        g_pos[i] = start;
        g_re[i] = start + cnt;
    }
}

__global__ void fill_kernel(const void* __restrict__ eiv, int E, int n) {
    int e = blockIdx.x * blockDim.x + threadIdx.x;
    if (e >= E) return;
    int r, c;
    read_edge(eiv, e, E, r, c);
    if ((unsigned)r < (unsigned)n && (unsigned)c < (unsigned)n) {
        int p = atomicAdd(&g_pos[r], 1);
        if (p < EMAX) g_col[p] = c;
    }
}

// ======================= gather: warp per node, no atomics ======================
// g_buf1[v] = (1+eps)*x[v] + sum_{c in N(v)} x[c]
__global__ void gather_kernel(const float* __restrict__ x, const float* __restrict__ eps, int n) {
    int w = (blockIdx.x * blockDim.x + threadIdx.x) >> 5;
    int lane = threadIdx.x & 31;
    if (w >= n) return;
    const float4* xb = (const float4*)x;
    float s = 1.f + __ldg(eps);
    float4 a = __ldg(xb + (size_t)w * 32 + lane);
    a.x *= s; a.y *= s; a.z *= s; a.w *= s;
    int j = g_rs[w], e = g_re[w];
    for (; j + 4 <= e; j += 4) {
        int c0 = __ldg(g_col + j);
        int c1 = __ldg(g_col + j + 1);
        int c2 = __ldg(g_col + j + 2);
        int c3 = __ldg(g_col + j + 3);
        float4 t0 = __ldg(xb + (size_t)c0 * 32 + lane);
        float4 t1 = __ldg(xb + (size_t)c1 * 32 + lane);
        float4 t2 = __ldg(xb + (size_t)c2 * 32 + lane);
        float4 t3 = __ldg(xb + (size_t)c3 * 32 + lane);
        a.x += t0.x + t1.x + t2.x + t3.x;
        a.y += t0.y + t1.y + t2.y + t3.y;
        a.z += t0.z + t1.z + t2.z + t3.z;
        a.w += t0.w + t1.w + t2.w + t3.w;
    }
    for (; j < e; j++) {
        int c = __ldg(g_col + j);
        float4 t = __ldg(xb + (size_t)c * 32 + lane);
        a.x += t.x; a.y += t.y; a.z += t.z; a.w += t.w;
    }
    ((float4*)g_buf1)[(size_t)w * 32 + lane] = a;
}

// ======================= bf16 split-MMA GEMM + BN stats (pipelined) =============
#define SM_SUM 0
#define SM_SQ  128
#define SM_BN  256
#define SM_AH  512
#define SM_AL  (512 + 4096)
#define SM_B   (512 + 8192)
#define SMEM_FLOATS (512 + 8192 + 16384)   // 25088 floats = 100352 B

template <int LAYER>
__global__ __launch_bounds__(256, 2) void gemm_tc(const float* __restrict__ bias,
                                                  const float* __restrict__ gamma1,
                                                  const float* __restrict__ beta1,
                                                  float* __restrict__ outParam, int n, float invN) {
    extern __shared__ float smf[];
    uint32_t* sAh = (uint32_t*)(smf + SM_AH);
    uint32_t* sAl = (uint32_t*)(smf + SM_AL);
    const uint4* B4 = (const uint4*)(smf + SM_B);
    const uint4* A4h = (const uint4*)sAh;
    const uint4* A4l = (const uint4*)sAl;
    float* sBn = smf + SM_BN;

    int tid = threadIdx.x, wid = tid >> 5, lane = tid & 31;
    int warpM = wid & 3, warpN = wid >> 2;
    int row0 = blockIdx.x * 128;

    const float* A = (LAYER == 1) ? g_buf1 : g_buf2;
    const uint4* Bimg = g_Bimg + (LAYER == 1 ? 0 : 4096);
    float* Out = (LAYER == 1) ? g_buf2 : outParam;
    float* gSum = g_stats + (LAYER == 1 ? 0 : 256);
    float* gSq  = g_stats + (LAYER == 1 ? 128 : 384);

    if (tid < 128) {
        smf[SM_SUM + tid] = 0.f;
        smf[SM_SQ + tid] = 0.f;
        if (LAYER == 2) {  // fold BN1 finalize into prologue
            float sum = g_stats[tid], sq = g_stats[128 + tid];
            float mean = sum * invN;
            float var = sq * invN - mean * mean;
            float sc = __ldg(gamma1 + tid) * rsqrtf(var + 1e-5f);
            sBn[tid] = sc;
            sBn[128 + tid] = __ldg(beta1 + tid) - mean * sc;
        }
    }
    {
        uint4* dst = (uint4*)(smf + SM_B);
        #pragma unroll
        for (int i = 0; i < 16; i++) dst[tid + 256 * i] = __ldg(Bimg + tid + 256 * i);
    }
    __syncthreads();

    int mld = tid >> 3;
    int f4c = tid & 7;
    auto ldA = [&](int kc, float4* v) {
        #pragma unroll
        for (int i = 0; i < 4; i++) {
            int m = mld + 32 * i;
            int gr = row0 + m;
            v[i] = make_float4(0.f, 0.f, 0.f, 0.f);
            if (gr < n) v[i] = __ldg((const float4*)(A + (size_t)gr * DF) + kc * 8 + f4c);
        }
    };
    auto cvA = [&](int buf, int kc, float4* v) {
        #pragma unroll
        for (int i = 0; i < 4; i++) {
            int m = mld + 32 * i;
            float4 w = v[i];
            if (LAYER == 2) {
                int c = (kc * 8 + f4c) * 4;
                w.x = fmaxf(fmaf(w.x, sBn[c + 0], sBn[128 + c + 0]), 0.f);
                w.y = fmaxf(fmaf(w.y, sBn[c + 1], sBn[128 + c + 1]), 0.f);
                w.z = fmaxf(fmaf(w.z, sBn[c + 2], sBn[128 + c + 2]), 0.f);
                w.w = fmaxf(fmaf(w.w, sBn[c + 3], sBn[128 + c + 3]), 0.f);
            }
            int g = m >> 4, mr = m & 15;
            int kstep = f4c >> 2, f2 = f4c & 3;
            int L0 = (mr & 7) * 4 + (f2 & 1) * 2;
            int r = (((f2 >> 1) & 1) << 1) + (mr >> 3);
            uint32_t h01 = pack2(w.x, w.y);
            uint32_t h23 = pack2(w.z, w.w);
            __nv_bfloat162* hp01 = (__nv_bfloat162*)&h01;
            __nv_bfloat162* hp23 = (__nv_bfloat162*)&h23;
            uint32_t l01 = pack2(w.x - __bfloat162float(hp01->x), w.y - __bfloat162float(hp01->y));
            uint32_t l23 = pack2(w.z - __bfloat162float(hp23->x), w.w - __bfloat162float(hp23->y));
            int base = buf * 2048 + ((g * 2 + kstep) * 32 + L0) * 4 + r;
            sAh[base] = h01;
            sAh[base + 4] = h23;
            sAl[base] = l01;
            sAl[base + 4] = l23;
        }
    };

    float acc[2][8][4];
    #pragma unroll
    for (int mt = 0; mt < 2; mt++)
        #pragma unroll
        for (int nt = 0; nt < 8; nt++)
            #pragma unroll
            for (int j = 0; j < 4; j++) acc[mt][nt][j] = 0.f;

    int g0 = warpM * 2;
    float4 v[4];
    ldA(0, v);
    cvA(0, 0, v);
    ldA(1, v);
    __syncthreads();

    #pragma unroll
    for (int kc = 0; kc < 4; kc++) {
        if (kc < 3) {
            cvA((kc + 1) & 1, kc + 1, v);
            if (kc < 2) ldA(kc + 2, v);
        }
        int bofs = (kc & 1) * 512;
        #pragma unroll
        for (int kk = 0; kk < 2; kk++) {
            int ksG = kc * 2 + kk;
            uint4 ah0 = A4h[bofs + (g0 * 2 + kk) * 32 + lane];
            uint4 al0 = A4l[bofs + (g0 * 2 + kk) * 32 + lane];
            uint4 ah1 = A4h[bofs + ((g0 + 1) * 2 + kk) * 32 + lane];
            uint4 al1 = A4l[bofs + ((g0 + 1) * 2 + kk) * 32 + lane];
            #pragma unroll
            for (int h = 0; h < 2; h++) {
                uint4 b0 = B4[((warpN * 8 + h * 4 + 0) * 8 + ksG) * 32 + lane];
                uint4 b1 = B4[((warpN * 8 + h * 4 + 1) * 8 + ksG) * 32 + lane];
                uint4 b2 = B4[((warpN * 8 + h * 4 + 2) * 8 + ksG) * 32 + lane];
                uint4 b3 = B4[((warpN * 8 + h * 4 + 3) * 8 + ksG) * 32 + lane];
                int nb = h * 4;
                mma16(acc[0][nb + 0], ah0, b0.x, b0.y);
                mma16(acc[0][nb + 1], ah0, b1.x, b1.y);
                mma16(acc[0][nb + 2], ah0, b2.x, b2.y);
                mma16(acc[0][nb + 3], ah0, b3.x, b3.y);
                mma16(acc[1][nb + 0], ah1, b0.x, b0.y);
                mma16(acc[1][nb + 1], ah1, b1.x, b1.y);
                mma16(acc[1][nb + 2], ah1, b2.x, b2.y);
                mma16(acc[1][nb + 3], ah1, b3.x, b3.y);
                mma16(acc[0][nb + 0], al0, b0.x, b0.y);
                mma16(acc[0][nb + 1], al0, b1.x, b1.y);
                mma16(acc[0][nb + 2], al0, b2.x, b2.y);
                mma16(acc[0][nb + 3], al0, b3.x, b3.y);
                mma16(acc[1][nb + 0], al1, b0.x, b0.y);
                mma16(acc[1][nb + 1], al1, b1.x, b1.y);
                mma16(acc[1][nb + 2], al1, b2.x, b2.y);
                mma16(acc[1][nb + 3], al1, b3.x, b3.y);
                mma16(acc[0][nb + 0], ah0, b0.z, b0.w);
                mma16(acc[0][nb + 1], ah0, b1.z, b1.w);
                mma16(acc[0][nb + 2], ah0, b2.z, b2.w);
                mma16(acc[0][nb + 3], ah0, b3.z, b3.w);
                mma16(acc[1][nb + 0], ah1, b0.z, b0.w);
                mma16(acc[1][nb + 1], ah1, b1.z, b1.w);
                mma16(acc[1][nb + 2], ah1, b2.z, b2.w);
                mma16(acc[1][nb + 3], ah1, b3.z, b3.w);
            }
        }
        __syncthreads();
    }

    // ---------------- epilogue: bias, store, BN stats ----------------
    float cs[16], cq[16];
    #pragma unroll
    for (int j = 0; j < 16; j++) { cs[j] = 0.f; cq[j] = 0.f; }

    int rbase = row0 + warpM * 32 + (lane >> 2);
    #pragma unroll
    for (int nt = 0; nt < 8; nt++) {
        int C = warpN * 64 + nt * 8 + (lane & 3) * 2;
        float2 bb = __ldg((const float2*)(bias + C));
        #pragma unroll
        for (int mt = 0; mt < 2; mt++) {
            int R0 = rbase + mt * 16;
            int R1 = R0 + 8;
            float v00 = acc[mt][nt][0] + bb.x;
            float v01 = acc[mt][nt][1] + bb.y;
            float v10 = acc[mt][nt][2] + bb.x;
            float v11 = acc[mt][nt][3] + bb.y;
            if (R0 < n) {
                *(float2*)(Out + (size_t)R0 * DF + C) = make_float2(v00, v01);
                cs[nt * 2] += v00;     cq[nt * 2] += v00 * v00;
                cs[nt * 2 + 1] += v01; cq[nt * 2 + 1] += v01 * v01;
            }
            if (R1 < n) {
                *(float2*)(Out + (size_t)R1 * DF + C) = make_float2(v10, v11);
                cs[nt * 2] += v10;     cq[nt * 2] += v10 * v10;
                cs[nt * 2 + 1] += v11; cq[nt * 2 + 1] += v11 * v11;
            }
        }
    }
    #pragma unroll
    for (int off = 4; off < 32; off <<= 1) {
        #pragma unroll
        for (int j = 0; j < 16; j++) {
            cs[j] += __shfl_xor_sync(0xFFFFFFFF, cs[j], off);
            cq[j] += __shfl_xor_sync(0xFFFFFFFF, cq[j], off);
        }
    }
    if (lane < 4) {
        #pragma unroll
        for (int nt = 0; nt < 8; nt++) {
            int C = warpN * 64 + nt * 8 + lane * 2;
            atomicAdd(&smf[SM_SUM + C], cs[nt * 2]);
            atomicAdd(&smf[SM_SUM + C + 1], cs[nt * 2 + 1]);
            atomicAdd(&smf[SM_SQ + C], cq[nt * 2]);
            atomicAdd(&smf[SM_SQ + C + 1], cq[nt * 2 + 1]);
        }
    }
    __syncthreads();
    if (tid < 128) {
        atomicAdd(&gSum[tid], smf[SM_SUM + tid]);
        atomicAdd(&gSq[tid],  smf[SM_SQ + tid]);
    }
}

// ======================= final BN2 + ReLU (finalize fused per-block) ===========
__global__ void apply_kernel(float* __restrict__ out, const float* __restrict__ gamma2,
                             const float* __restrict__ beta2, int n32, float invN) {
    __shared__ float sc[128], sh[128];
    int tid = threadIdx.x;
    if (tid < 128) {
        float sum = g_stats[256 + tid], sq = g_stats[384 + tid];
        float mean = sum * invN;
        float var = sq * invN - mean * mean;
        float s = __ldg(gamma2 + tid) * rsqrtf(var + 1e-5f);
        sc[tid] = s;
        sh[tid] = __ldg(beta2 + tid) - mean * s;
    }
    __syncthreads();
    int i = blockIdx.x * blockDim.x + tid;
    if (i >= n32) return;
    int c = (i & 31) * 4;
    float4 v = ((float4*)out)[i];
    v.x = fmaxf(fmaf(v.x, sc[c + 0], sh[c + 0]), 0.f);
    v.y = fmaxf(fmaf(v.y, sc[c + 1], sh[c + 1]), 0.f);
    v.z = fmaxf(fmaf(v.z, sc[c + 2], sh[c + 2]), 0.f);
    v.w = fmaxf(fmaf(v.w, sc[c + 3], sh[c + 3]), 0.f);
    ((float4*)out)[i] = v;
}

// ======================= launch =======================
extern "C" void kernel_launch(void* const* d_in, const int* in_sizes, int n_in,
                              void* d_out, int out_size) {
    const float* x      = (const float*)d_in[0];
    const void* ei      = d_in[1];
    const float* eps    = (const float*)d_in[2];
    const float* W1     = (const float*)d_in[3];
    const float* b1     = (const float*)d_in[4];
    const float* gamma1 = (const float*)d_in[5];
    const float* beta1  = (const float*)d_in[6];
    const float* W2     = (const float*)d_in[7];
    const float* b2     = (const float*)d_in[8];
    const float* gamma2 = (const float*)d_in[9];
    const float* beta2  = (const float*)d_in[10];
    float* out = (float*)d_out;

    int n   = in_sizes[0] / DF;
    int E   = in_sizes[1] / 2;
    int n32 = n * (DF / 4);
    float invN = 1.f / (float)n;

    const int SMEM = SMEM_FLOATS * 4;  // 100352 bytes
    cudaFuncSetAttribute(gemm_tc<1>, cudaFuncAttributeMaxDynamicSharedMemorySize, SMEM);
    cudaFuncSetAttribute(gemm_tc<2>, cudaFuncAttributeMaxDynamicSharedMemorySize, SMEM);

    int NBZ = (n + 255) / 256;
    int EB = (E + 255) / 256;

    prep0<<<NBZ + 2, 256>>>(W1, W2, (const int*)ei, n, NBZ);
    hist_kernel<<<EB, 256>>>(ei, E, n);
    offsets_kernel<<<NBZ, 256>>>(n);
    fill_kernel<<<EB, 256>>>(ei, E, n);
    gather_kernel<<<(n * 32 + 255) / 256, 256>>>(x, eps, n);

    int gblocks = (n + 127) / 128;
    gemm_tc<1><<<gblocks, 256, SMEM>>>(b1, nullptr, nullptr, nullptr, n, invN);
    gemm_tc<2><<<gblocks, 256, SMEM>>>(b2, gamma1, beta1, out, n, invN);
    apply_kernel<<<(n32 + 255) / 256, 256>>>(out, gamma2, beta2, n32, invN);
}